// round 12
// baseline (speedup 1.0000x reference)
#include <cuda_runtime.h>
#include <cuda_fp16.h>
#include <math.h>
#include <stddef.h>
#include <stdint.h>

#define B_SZ   4
#define S_SZ   1024
#define D_M    1024
#define H_N    16
#define D_INT  64
#define D_V    128
#define HID    4096
#define NTOK   4096
#define HB     64
#define LAMBDA_INIT 0.3555090675909693f
#define HEADLN_SCALE 0.6444909324090307f
#define R2_ELEMS 4194304
#define FULL_ELEMS 71303168

// ======================= helpers =======================
__device__ __forceinline__ uint32_t smem_u32(const void* p) {
    uint32_t a;
    asm("{ .reg .u64 t; cvta.to.shared.u64 t, %1; cvt.u32.u64 %0, t; }" : "=r"(a) : "l"(p));
    return a;
}
#define CP_ASYNC16(sdst, gsrc) \
    asm volatile("cp.async.cg.shared.global [%0], [%1], 16;" :: "r"(sdst), "l"(gsrc) : "memory")
#define CP_COMMIT() asm volatile("cp.async.commit_group;" ::: "memory")
template<int N> __device__ __forceinline__ void cp_waitg() {
    asm volatile("cp.async.wait_group %0;" :: "n"(N) : "memory");
}

__device__ __forceinline__ void mma_f16(float* d, uint32_t a0, uint32_t a1, uint32_t a2,
                                        uint32_t a3, uint32_t b0, uint32_t b1) {
    asm volatile(
        "mma.sync.aligned.m16n8k16.row.col.f32.f16.f16.f32 "
        "{%0,%1,%2,%3}, {%4,%5,%6,%7}, {%8,%9}, {%0,%1,%2,%3};"
        : "+f"(d[0]), "+f"(d[1]), "+f"(d[2]), "+f"(d[3])
        : "r"(a0), "r"(a1), "r"(a2), "r"(a3), "r"(b0), "r"(b1));
}
__device__ __forceinline__ void ldmx4(uint32_t* r, uint32_t addr) {
    asm volatile("ldmatrix.sync.aligned.m8n8.x4.shared.b16 {%0,%1,%2,%3}, [%4];"
        : "=r"(r[0]), "=r"(r[1]), "=r"(r[2]), "=r"(r[3]) : "r"(addr));
}
__device__ __forceinline__ void ldmx2(uint32_t* r, uint32_t addr) {
    asm volatile("ldmatrix.sync.aligned.m8n8.x2.shared.b16 {%0,%1}, [%2];"
        : "=r"(r[0]), "=r"(r[1]) : "r"(addr));
}
__device__ __forceinline__ uint32_t packh2(float a, float b) {
    __half2 p; p.x = __float2half(a); p.y = __float2half(b);
    return *reinterpret_cast<uint32_t*>(&p);
}

// ======================= static scratch =======================
__device__ __align__(16) __half  g_QKh  [(size_t)NTOK * 2048];   // Q|K fp16 hi
__device__ __align__(16) __half  g_QKl  [(size_t)NTOK * 2048];   // Q|K fp16 lo
__device__ __align__(16) __half  g_Bqh  [(size_t)2048 * 1024];   // WQ|WK K-major fp16 hi
__device__ __align__(16) __half  g_WVh  [(size_t)2048 * 1024];
__device__ __align__(16) __half  g_WOth [(size_t)1024 * 2048];
__device__ __align__(16) __half  g_W1th [(size_t)4096 * 1024];
__device__ __align__(16) __half  g_W2th [(size_t)1024 * 4096];
__device__ __align__(16) float   g_biasqk[2048];
__device__ __align__(16) __half  g_xhf  [(size_t)NTOK * 1024];
__device__ __align__(16) __half  g_xlf  [(size_t)NTOK * 1024];
__device__ __align__(16) __half  g_Sh   [(size_t)HB * S_SZ * S_SZ];  // scores fp16
__device__ __align__(16) __half  g_Ah   [(size_t)HB * S_SZ * S_SZ];  // A fp16 hi
__device__ __align__(16) __half  g_Vh   [(size_t)NTOK * 2048];
__device__ __align__(16) __half  g_Vth  [(size_t)HB * 128 * 1024];
__device__ __align__(16) float   g_O    [(size_t)HB * S_SZ * D_V];
__device__ __align__(16) __half  g_Och  [(size_t)NTOK * 2048];
__device__ __align__(16) float   g_h1pre[(size_t)NTOK * D_M];
__device__ __align__(16) float   g_h1   [(size_t)NTOK * D_M];
__device__ __align__(16) __half  g_h1h  [(size_t)NTOK * D_M];
__device__ __align__(16) __half  g_ffhh [(size_t)NTOK * HID];
__device__ __align__(16) float   g_r2pre[(size_t)NTOK * D_M];
__device__ float g_lamscale;

// ======================= lambda =======================
__global__ void lam_kernel(const float* __restrict__ lq1, const float* __restrict__ lk1,
                           const float* __restrict__ lq2, const float* __restrict__ lk2)
{
    __shared__ float s1[64], s2[64];
    int t = threadIdx.x;
    s1[t] = lq1[t] * lk1[t];
    s2[t] = lq2[t] * lk2[t];
    __syncthreads();
    if (t == 0) {
        float d1 = 0.f, d2 = 0.f;
        for (int i = 0; i < 64; i++) { d1 += s1[i]; d2 += s2[i]; }
        g_lamscale = 1.0f - (expf(d1) - expf(d2) + LAMBDA_INIT);
    }
}

// ======================= conversions =======================
// x -> fp16 hi/lo
__global__ void __launch_bounds__(256) conv_hilo_f16(
    const float* __restrict__ in, __half* __restrict__ oh, __half* __restrict__ ol, int n4)
{
    int i = blockIdx.x * 256 + threadIdx.x;
    if (i >= n4) return;
    float4 v = reinterpret_cast<const float4*>(in)[i];
    float vv[4] = {v.x, v.y, v.z, v.w};
    uint32_t fh[2], fl[2];
#pragma unroll
    for (int p = 0; p < 2; p++) {
        float a = vv[p * 2], b = vv[p * 2 + 1];
        float ha = __half2float(__float2half(a)), hb = __half2float(__float2half(b));
        fh[p] = packh2(a, b);
        fl[p] = packh2(a - ha, b - hb);
    }
    reinterpret_cast<uint32_t*>(oh)[i * 2] = fh[0];  reinterpret_cast<uint32_t*>(oh)[i * 2 + 1] = fh[1];
    reinterpret_cast<uint32_t*>(ol)[i * 2] = fl[0];  reinterpret_cast<uint32_t*>(ol)[i * 2 + 1] = fl[1];
}

// weight transpose-convert (fp16 hi only): out[n][k] from in[(n/dout)*K*dout + k*dout + n%dout]
__global__ void convW(const float* __restrict__ in, __half* __restrict__ oh, int K, int dout)
{
    __shared__ float t[32][33];
    int k0 = blockIdx.x * 32, n0 = blockIdx.y * 32;
    int h = n0 / dout, d0 = n0 - h * dout;
    const float* src = in + (size_t)h * K * dout + d0;
    for (int r = threadIdx.y; r < 32; r += 8)
        t[r][threadIdx.x] = src[(size_t)(k0 + r) * dout + threadIdx.x];
    __syncthreads();
    for (int r = threadIdx.y; r < 32; r += 8)
        oh[(size_t)(n0 + r) * K + k0 + threadIdx.x] = __float2half(t[threadIdx.x][r]);
}

// V transpose (fp16 hi): Vt[z][v][t] from Vh[(b*1024+t)*2048 + h*128 + v]
__global__ void convVt_f16(const __half* __restrict__ sh, __half* __restrict__ oh)
{
    __shared__ __half th[32][33];
    int z = blockIdx.z, h = z >> 2, b = z & 3;
    int t0 = blockIdx.x * 32, v0 = blockIdx.y * 32;
    for (int r = threadIdx.y; r < 32; r += 8)
        th[r][threadIdx.x] = sh[(size_t)(b * 1024 + t0 + r) * 2048 + h * 128 + v0 + threadIdx.x];
    __syncthreads();
    size_t base = (size_t)z * 131072;
    for (int r = threadIdx.y; r < 32; r += 8)
        oh[base + (size_t)(v0 + r) * 1024 + t0 + threadIdx.x] = th[threadIdx.x][r];
}

__global__ void concat_bias2(const float* __restrict__ bq, const float* __restrict__ bk,
                             float* __restrict__ o)
{
    int t = blockIdx.x * 256 + threadIdx.x;
    if (t < 1024) o[t] = bq[t];
    else if (t < 2048) o[t] = bk[t - 1024];
}

// ======================= tensor-core GEMM (fp16 mma.sync) ====================
// C[128x128 tile] = sum_k A[m][k]*B[n][k], K-major fp16.
// TERMS: 2 = Ah*Bh + Al*Bh ; 1 = Ah*Bh only.
// NS: cp.async pipeline depth. modes: 0 plain; 1 scores batched; 2 AV batched.
template<int TERMS, int NS>
__global__ void __launch_bounds__(256, 2) gemm_mma(
    const __half* __restrict__ Ah, const __half* __restrict__ Al,
    const __half* __restrict__ Bh,
    const float* __restrict__ bias, const float* __restrict__ res,
    float* __restrict__ cout, __half* __restrict__ outh, __half* __restrict__ outl,
    int K, int lda, int ldb, int ldc, float alpha, int relu, int mode)
{
    constexpr int NTILE = TERMS + 1;
    constexpr int STG = NTILE * 10240;
    constexpr uint32_t oAl = 10240;
    constexpr uint32_t oBh = (TERMS >= 2) ? 20480u : 10240u;
    extern __shared__ char dsm[];
    const int tid = threadIdx.x;
    const int lane = tid & 31, wid = tid >> 5;
    const int wy = wid >> 2, wx = wid & 3;       // warp tile: 64(M) x 32(N)
    const int m0 = blockIdx.y * 128, n0 = blockIdx.x * 128;
    const uint32_t smbase = smem_u32(dsm);

    size_t aoff = 0, boff = 0, coff = 0;
    if (mode == 1) {
        int z = blockIdx.z, h = z >> 2, b = z & 3;
        aoff = (size_t)(b << 10) * lda + (h << 6);
        boff = (size_t)(b << 10) * ldb + (h << 6);
        coff = (size_t)z << 20;
    } else if (mode == 2) {
        int z = blockIdx.z;
        aoff = (size_t)z << 20;
        boff = (size_t)z << 17;
        coff = (size_t)z << 17;
    }

    float acc[4][4][4];
#pragma unroll
    for (int i = 0; i < 4; i++)
#pragma unroll
        for (int j = 0; j < 4; j++)
#pragma unroll
            for (int q = 0; q < 4; q++) acc[i][j][q] = 0.f;

    const int niter = K >> 5;

    auto issue_tile = [&](int it, int slot) {
        int k0 = it << 5;
        uint32_t sb = smbase + slot * STG;
#pragma unroll
        for (int i = 0; i < 2; i++) {
            int l = tid + (i << 8);
            int row = l >> 2, c16 = l & 3;
            size_t aidx = aoff + (size_t)(m0 + row) * lda + k0 + (c16 << 3);
            size_t bidx = boff + (size_t)(n0 + row) * ldb + k0 + (c16 << 3);
            uint32_t so = (uint32_t)(row * 80 + (c16 << 4));
            CP_ASYNC16(sb + so,       Ah + aidx);
            if (TERMS >= 2) CP_ASYNC16(sb + oAl + so, Al + aidx);
            CP_ASYNC16(sb + oBh + so, Bh + bidx);
        }
        CP_COMMIT();
    };

#pragma unroll
    for (int s = 0; s < NS - 1; s++)
        if (s < niter) issue_tile(s, s);

    // ldmatrix per-lane addressing
    const int a_row = (wy << 6) + (lane & 7) + ((lane >> 3) & 1) * 8;  // + mt*16
    const int a_kb  = (lane >> 4) << 4;                                // + ks*32
    const int l15 = lane & 15;
    const int b_row = (wx << 5) + (l15 & 7);                           // + nt*8
    const int b_kb  = (l15 >> 3) << 4;                                 // + ks*32

    int cs = 0, is_ = NS - 1;
#pragma unroll 1
    for (int it = 0; it < niter; it++) {
        if (it + NS - 1 < niter) {
            issue_tile(it + NS - 1, is_);
            cp_waitg<NS - 1>();
        } else {
            cp_waitg<0>();
        }
        __syncthreads();

        uint32_t base = smbase + cs * STG;
        uint32_t pAh = base;
        uint32_t pAl = base + oAl;
        uint32_t pBh = base + oBh;

#pragma unroll
        for (int ks = 0; ks < 2; ks++) {
            const int ksb = ks << 5;
            uint32_t bhf[4][2];
#pragma unroll
            for (int nt = 0; nt < 4; nt++) {
                uint32_t bo = (uint32_t)((b_row + (nt << 3)) * 80 + ksb + b_kb);
                ldmx2(bhf[nt], pBh + bo);
            }
#pragma unroll
            for (int mt = 0; mt < 4; mt++) {
                uint32_t ao = (uint32_t)((a_row + (mt << 4)) * 80 + ksb + a_kb);
                uint32_t ahf[4], alf[4];
                ldmx4(ahf, pAh + ao);
                if (TERMS >= 2) ldmx4(alf, pAl + ao);
#pragma unroll
                for (int nt = 0; nt < 4; nt++) {
                    mma_f16(acc[mt][nt], ahf[0], ahf[1], ahf[2], ahf[3], bhf[nt][0], bhf[nt][1]);
                    if (TERMS >= 2)
                        mma_f16(acc[mt][nt], alf[0], alf[1], alf[2], alf[3], bhf[nt][0], bhf[nt][1]);
                }
            }
        }
        __syncthreads();
        cs = (cs + 1 == NS) ? 0 : cs + 1;
        is_ = (is_ + 1 == NS) ? 0 : is_ + 1;
    }

    // epilogue: alpha, bias, residual, relu; fp32 and/or fp16 hi(/lo) outputs
#pragma unroll
    for (int mt = 0; mt < 4; mt++) {
#pragma unroll
        for (int nt = 0; nt < 4; nt++) {
#pragma unroll
            for (int hf = 0; hf < 2; hf++) {
                int row = m0 + (wy << 6) + (mt << 4) + (lane >> 2) + (hf << 3);
                int col = n0 + (wx << 5) + (nt << 3) + ((lane & 3) << 1);
                float v0 = acc[mt][nt][hf * 2]     * alpha;
                float v1 = acc[mt][nt][hf * 2 + 1] * alpha;
                if (bias) { v0 += bias[col]; v1 += bias[col + 1]; }
                if (res) {
                    float2 rv = *reinterpret_cast<const float2*>(res + (size_t)row * ldc + col);
                    v0 += rv.x; v1 += rv.y;
                }
                if (relu) { v0 = fmaxf(v0, 0.f); v1 = fmaxf(v1, 0.f); }
                size_t oidx = coff + (size_t)row * ldc + col;
                if (cout) *reinterpret_cast<float2*>(cout + oidx) = make_float2(v0, v1);
                if (outh) {
                    *reinterpret_cast<uint32_t*>(outh + oidx) = packh2(v0, v1);
                    if (outl) {
                        float h0 = __half2float(__float2half(v0));
                        float h1 = __half2float(__float2half(v1));
                        *reinterpret_cast<uint32_t*>(outl + oidx) = packh2(v0 - h0, v1 - h1);
                    }
                }
            }
        }
    }
}

// ======================= softmax (fp16 scores in; fp32 A + fp16 hi out) =====
__global__ void __launch_bounds__(256) softmax_row(
    const __half* __restrict__ Sc, const int* __restrict__ mask, float* __restrict__ Aout,
    __half* __restrict__ Ahi)
{
    __shared__ float red[8];
    __shared__ float bcast;
    size_t row = blockIdx.x;
    int b = (int)((row >> 10) & 3);
    const __half* in = Sc + row * 1024;
    const int* mrow = mask + b * 1024;
    int t = threadIdx.x;
    int wid = t >> 5, lane = t & 31;

    float v[4];
    float mx = -INFINITY;
#pragma unroll
    for (int i = 0; i < 4; i++) {
        int c = t + i * 256;
        float val = __half2float(in[c]);
        if (mrow[c] == 0) val = -INFINITY;
        v[i] = val;
        mx = fmaxf(mx, val);
    }
#pragma unroll
    for (int o = 16; o; o >>= 1) mx = fmaxf(mx, __shfl_xor_sync(0xffffffffu, mx, o));
    if (lane == 0) red[wid] = mx;
    __syncthreads();
    if (t < 32) {
        float m2 = (t < 8) ? red[t] : -INFINITY;
#pragma unroll
        for (int o = 4; o; o >>= 1) m2 = fmaxf(m2, __shfl_xor_sync(0xffffffffu, m2, o));
        if (t == 0) bcast = m2;
    }
    __syncthreads();
    mx = bcast;

    float sum = 0.f;
#pragma unroll
    for (int i = 0; i < 4; i++) { v[i] = expf(v[i] - mx); sum += v[i]; }
#pragma unroll
    for (int o = 16; o; o >>= 1) sum += __shfl_xor_sync(0xffffffffu, sum, o);
    __syncthreads();
    if (lane == 0) red[wid] = sum;
    __syncthreads();
    if (t < 32) {
        float s2 = (t < 8) ? red[t] : 0.f;
#pragma unroll
        for (int o = 4; o; o >>= 1) s2 += __shfl_xor_sync(0xffffffffu, s2, o);
        if (t == 0) bcast = g_lamscale / s2;
    }
    __syncthreads();
    float sc = bcast;
#pragma unroll
    for (int i = 0; i < 4; i++) {
        size_t idx = row * 1024 + t + i * 256;
        float vv = v[i] * sc;
        Aout[idx] = vv;
        Ahi[idx] = __float2half(vv);
    }
}

// ======================= per-head LN(128) + concat, emits fp16 hi ===========
__global__ void __launch_bounds__(256) headln_kernel(
    const float* __restrict__ O, const float* __restrict__ w,
    const float* __restrict__ bvec, __half* __restrict__ och)
{
    int gw = blockIdx.x * 8 + (threadIdx.x >> 5);
    int lane = threadIdx.x & 31;
    const float* xr = O + (size_t)gw * 128;
    float x0 = xr[lane], x1 = xr[lane + 32], x2 = xr[lane + 64], x3 = xr[lane + 96];
    float s = x0 + x1 + x2 + x3;
#pragma unroll
    for (int o = 16; o; o >>= 1) s += __shfl_xor_sync(0xffffffffu, s, o);
    float mean = s * (1.f / 128.f);
    float d0 = x0 - mean, d1 = x1 - mean, d2 = x2 - mean, d3 = x3 - mean;
    float q = d0 * d0 + d1 * d1 + d2 * d2 + d3 * d3;
#pragma unroll
    for (int o = 16; o; o >>= 1) q += __shfl_xor_sync(0xffffffffu, q, o);
    float rstd = rsqrtf(q * (1.f / 128.f) + 1e-5f);

    int z = gw >> 10, s_ = gw & 1023;
    int h = z >> 2, b = z & 3;
    size_t base = ((size_t)(b * S_SZ + s_)) * 2048 + h * 128;
    float vals[4] = {
        (d0 * rstd * w[lane]      + bvec[lane])      * HEADLN_SCALE,
        (d1 * rstd * w[lane + 32] + bvec[lane + 32]) * HEADLN_SCALE,
        (d2 * rstd * w[lane + 64] + bvec[lane + 64]) * HEADLN_SCALE,
        (d3 * rstd * w[lane + 96] + bvec[lane + 96]) * HEADLN_SCALE };
#pragma unroll
    for (int i = 0; i < 4; i++)
        och[base + lane + i * 32] = __float2half(vals[i]);
}

// ======================= LayerNorm 1024 (optional fp16 hi out) ==============
__global__ void __launch_bounds__(256) ln1024(
    const float* __restrict__ X, const float* __restrict__ w,
    const float* __restrict__ bvec, float* __restrict__ out,
    __half* __restrict__ outh)
{
    __shared__ float red[8];
    __shared__ float bc;
    size_t row = blockIdx.x;
    const float* xr = X + row * 1024;
    int t = threadIdx.x;
    int wid = t >> 5, lane = t & 31;

    float v[4];
    float s = 0.f;
#pragma unroll
    for (int i = 0; i < 4; i++) { v[i] = xr[t + i * 256]; s += v[i]; }
#pragma unroll
    for (int o = 16; o; o >>= 1) s += __shfl_xor_sync(0xffffffffu, s, o);
    if (lane == 0) red[wid] = s;
    __syncthreads();
    if (t < 32) {
        float s2 = (t < 8) ? red[t] : 0.f;
#pragma unroll
        for (int o = 4; o; o >>= 1) s2 += __shfl_xor_sync(0xffffffffu, s2, o);
        if (t == 0) bc = s2 * (1.f / 1024.f);
    }
    __syncthreads();
    float mean = bc;

    float q = 0.f;
#pragma unroll
    for (int i = 0; i < 4; i++) { float d = v[i] - mean; q += d * d; }
#pragma unroll
    for (int o = 16; o; o >>= 1) q += __shfl_xor_sync(0xffffffffu, q, o);
    __syncthreads();
    if (lane == 0) red[wid] = q;
    __syncthreads();
    if (t < 32) {
        float q2 = (t < 8) ? red[t] : 0.f;
#pragma unroll
        for (int o = 4; o; o >>= 1) q2 += __shfl_xor_sync(0xffffffffu, q2, o);
        if (t == 0) bc = rsqrtf(q2 * (1.f / 1024.f) + 1e-5f);
    }
    __syncthreads();
    float rstd = bc;
#pragma unroll
    for (int i = 0; i < 4; i++) {
        int c = t + i * 256;
        float vv = (v[i] - mean) * rstd * w[c] + bvec[c];
        out[row * 1024 + c] = vv;
        if (outh) outh[row * 1024 + c] = __float2half(vv);
    }
}

// ======================= host launcher ======================================
extern "C" void kernel_launch(void* const* d_in, const int* in_sizes, int n_in,
                              void* d_out, int out_size)
{
    const float* x    = (const float*)d_in[0];
    const int*   mask = (const int*)  d_in[1];
    const float* WQ1  = (const float*)d_in[2];
    const float* bQ1  = (const float*)d_in[3];
    const float* WK1  = (const float*)d_in[4];
    const float* bK1  = (const float*)d_in[5];
    const float* WV   = (const float*)d_in[6];
    const float* bV   = (const float*)d_in[7];
    const float* lnhw = (const float*)d_in[8];
    const float* lnhb = (const float*)d_in[9];
    const float* WO   = (const float*)d_in[10];
    const float* bO   = (const float*)d_in[11];
    const float* ln1w = (const float*)d_in[12];
    const float* ln1b = (const float*)d_in[13];
    const float* ln2w = (const float*)d_in[14];
    const float* ln2b = (const float*)d_in[15];
    const float* W1   = (const float*)d_in[16];
    const float* b1   = (const float*)d_in[17];
    const float* W2   = (const float*)d_in[18];
    const float* b2   = (const float*)d_in[19];
    const float* lq1  = (const float*)d_in[20];
    const float* lk1  = (const float*)d_in[21];
    const float* lq2  = (const float*)d_in[22];
    const float* lk2  = (const float*)d_in[23];

    float* out = (float*)d_out;

    const int SM2 = 3 * 3 * 10240;   // 92160: 2-term, 3-stage
    const int SM1 = 4 * 2 * 10240;   // 81920: 1-term, 4-stage
    cudaFuncSetAttribute(gemm_mma<2, 3>, cudaFuncAttributeMaxDynamicSharedMemorySize, SM2);
    cudaFuncSetAttribute(gemm_mma<1, 4>, cudaFuncAttributeMaxDynamicSharedMemorySize, SM1);

    float *op, *h1pre, *h1, *r2pre, *biasqk;
    __half *qkh, *qkl, *bqh, *wvh, *woth, *w1th, *w2th;
    __half *xhf, *xlf, *sh, *ah, *vh, *vth, *och, *h1h, *ffhh;
    cudaGetSymbolAddress((void**)&qkh,   g_QKh);
    cudaGetSymbolAddress((void**)&qkl,   g_QKl);
    cudaGetSymbolAddress((void**)&bqh,   g_Bqh);
    cudaGetSymbolAddress((void**)&wvh,   g_WVh);
    cudaGetSymbolAddress((void**)&woth,  g_WOth);
    cudaGetSymbolAddress((void**)&w1th,  g_W1th);
    cudaGetSymbolAddress((void**)&w2th,  g_W2th);
    cudaGetSymbolAddress((void**)&biasqk, g_biasqk);
    cudaGetSymbolAddress((void**)&xhf,   g_xhf);
    cudaGetSymbolAddress((void**)&xlf,   g_xlf);
    cudaGetSymbolAddress((void**)&sh,    g_Sh);
    cudaGetSymbolAddress((void**)&ah,    g_Ah);
    cudaGetSymbolAddress((void**)&vh,    g_Vh);
    cudaGetSymbolAddress((void**)&vth,   g_Vth);
    cudaGetSymbolAddress((void**)&op,    g_O);
    cudaGetSymbolAddress((void**)&och,   g_Och);
    cudaGetSymbolAddress((void**)&h1pre, g_h1pre);
    cudaGetSymbolAddress((void**)&h1,    g_h1);
    cudaGetSymbolAddress((void**)&h1h,   g_h1h);
    cudaGetSymbolAddress((void**)&ffhh,  g_ffhh);
    cudaGetSymbolAddress((void**)&r2pre, g_r2pre);

    float* A_ptr = (out_size >= FULL_ELEMS) ? (out + R2_ELEMS) : op;  // fp32 A dest

    lam_kernel<<<1, 64>>>(lq1, lk1, lq2, lk2);
    concat_bias2<<<8, 256>>>(bQ1, bK1, biasqk);

    // weight converts (fp16 hi, K-major)
    convW<<<dim3(32, 32),  dim3(32, 8)>>>(WQ1, bqh,               1024, 64);
    convW<<<dim3(32, 32),  dim3(32, 8)>>>(WK1, bqh + 1024 * 1024, 1024, 64);
    convW<<<dim3(32, 64),  dim3(32, 8)>>>(WV,  wvh,  1024, 128);
    convW<<<dim3(64, 32),  dim3(32, 8)>>>(WO,  woth, 2048, 1024);
    convW<<<dim3(32, 128), dim3(32, 8)>>>(W1,  w1th, 1024, 4096);
    convW<<<dim3(128, 32), dim3(32, 8)>>>(W2,  w2th, 4096, 1024);
    conv_hilo_f16<<<4096, 256>>>(x, xhf, xlf, 1048576);

    // QK projection (fp16 2-term): [4096, 2048], K=1024; emits hi+lo
    gemm_mma<2, 3><<<dim3(16, 32, 1), 256, SM2>>>(
        xhf, xlf, bqh, biasqk, nullptr, nullptr, qkh, qkl,
        1024, 1024, 1024, 2048, 1.0f, 0, 0);

    // V projection (fp16 2-term): [4096, 2048], K=1024, hi only
    gemm_mma<2, 3><<<dim3(16, 32, 1), 256, SM2>>>(
        xhf, xlf, wvh, bV, nullptr, nullptr, vh, nullptr,
        1024, 1024, 1024, 2048, 1.0f, 0, 0);

    // scores (fp16 2-term, Q hi/lo x K hi), batched; alpha = 1/sqrt(1024); fp16 out
    gemm_mma<2, 3><<<dim3(8, 8, 64), 256, SM2>>>(
        qkh, qkl, qkh + 1024, nullptr, nullptr, nullptr, sh, nullptr,
        64, 2048, 2048, 1024, 0.03125f, 0, 1);

    softmax_row<<<65536, 256>>>(sh, mask, A_ptr, ah);
    convVt_f16<<<dim3(32, 4, 64), dim3(32, 8)>>>(vh, vth);

    // AV (fp16 1-term), batched
    gemm_mma<1, 4><<<dim3(1, 8, 64), 256, SM1>>>(
        ah, nullptr, vth, nullptr, nullptr, op, nullptr, nullptr,
        1024, 1024, 1024, 128, 1.0f, 0, 2);

    headln_kernel<<<8192, 256>>>(op, lnhw, lnhb, och);

    // output projection (fp16 1-term) + residual(x), LN1
    gemm_mma<1, 4><<<dim3(8, 32, 1), 256, SM1>>>(
        och, nullptr, woth, bO, x, h1pre, nullptr, nullptr,
        2048, 2048, 2048, 1024, 1.0f, 0, 0);
    ln1024<<<4096, 256>>>(h1pre, ln1w, ln1b, h1, h1h);

    // FFN (fp16 1-term): relu(h1 @ W1 + b1) @ W2 + b2 + h1, LN2 -> out
    gemm_mma<1, 4><<<dim3(32, 32, 1), 256, SM1>>>(
        h1h, nullptr, w1th, b1, nullptr, nullptr, ffhh, nullptr,
        1024, 1024, 1024, 4096, 1.0f, 1, 0);
    gemm_mma<1, 4><<<dim3(8, 32, 1), 256, SM1>>>(
        ffhh, nullptr, w2th, b2, h1, r2pre, nullptr, nullptr,
        4096, 4096, 4096, 1024, 1.0f, 0, 0);
    ln1024<<<4096, 256>>>(r2pre, ln2w, ln2b, out, nullptr);
}

// round 13
// speedup vs baseline: 1.2215x; 1.2215x over previous
#include <cuda_runtime.h>
#include <cuda_fp16.h>
#include <math.h>
#include <stddef.h>
#include <stdint.h>

#define B_SZ   4
#define S_SZ   1024
#define D_M    1024
#define H_N    16
#define D_INT  64
#define D_V    128
#define HID    4096
#define NTOK   4096
#define HB     64
#define LAMBDA_INIT 0.3555090675909693f
#define HEADLN_SCALE 0.6444909324090307f
#define R2_ELEMS 4194304
#define FULL_ELEMS 71303168

// ======================= helpers =======================
__device__ __forceinline__ uint32_t smem_u32(const void* p) {
    uint32_t a;
    asm("{ .reg .u64 t; cvta.to.shared.u64 t, %1; cvt.u32.u64 %0, t; }" : "=r"(a) : "l"(p));
    return a;
}
#define CP_ASYNC16(sdst, gsrc) \
    asm volatile("cp.async.cg.shared.global [%0], [%1], 16;" :: "r"(sdst), "l"(gsrc) : "memory")
#define CP_COMMIT() asm volatile("cp.async.commit_group;" ::: "memory")
template<int N> __device__ __forceinline__ void cp_waitg() {
    asm volatile("cp.async.wait_group %0;" :: "n"(N) : "memory");
}

__device__ __forceinline__ void mma_f16(float* d, uint32_t a0, uint32_t a1, uint32_t a2,
                                        uint32_t a3, uint32_t b0, uint32_t b1) {
    asm volatile(
        "mma.sync.aligned.m16n8k16.row.col.f32.f16.f16.f32 "
        "{%0,%1,%2,%3}, {%4,%5,%6,%7}, {%8,%9}, {%0,%1,%2,%3};"
        : "+f"(d[0]), "+f"(d[1]), "+f"(d[2]), "+f"(d[3])
        : "r"(a0), "r"(a1), "r"(a2), "r"(a3), "r"(b0), "r"(b1));
}
__device__ __forceinline__ void ldmx4(uint32_t* r, uint32_t addr) {
    asm volatile("ldmatrix.sync.aligned.m8n8.x4.shared.b16 {%0,%1,%2,%3}, [%4];"
        : "=r"(r[0]), "=r"(r[1]), "=r"(r[2]), "=r"(r[3]) : "r"(addr));
}
__device__ __forceinline__ uint32_t packh2(float a, float b) {
    __half2 p; p.x = __float2half(a); p.y = __float2half(b);
    return *reinterpret_cast<uint32_t*>(&p);
}

// ======================= static scratch =======================
__device__ __align__(16) __half  g_QKh  [(size_t)NTOK * 2048];   // Q|K fp16 hi
__device__ __align__(16) __half  g_QKl  [(size_t)NTOK * 2048];   // Q|K fp16 lo
__device__ __align__(16) __half  g_Bqh  [(size_t)2048 * 1024];   // WQ|WK K-major fp16 hi
__device__ __align__(16) __half  g_WVh  [(size_t)2048 * 1024];
__device__ __align__(16) __half  g_WOth [(size_t)1024 * 2048];
__device__ __align__(16) __half  g_W1th [(size_t)4096 * 1024];
__device__ __align__(16) __half  g_W2th [(size_t)1024 * 4096];
__device__ __align__(16) float   g_biasqk[2048];
__device__ __align__(16) __half  g_xhf  [(size_t)NTOK * 1024];
__device__ __align__(16) __half  g_xlf  [(size_t)NTOK * 1024];
__device__ __align__(16) __half  g_Sh   [(size_t)HB * S_SZ * S_SZ];  // scores fp16
__device__ __align__(16) __half  g_Ah   [(size_t)HB * S_SZ * S_SZ];  // A fp16 hi
__device__ __align__(16) __half  g_Vh   [(size_t)NTOK * 2048];
__device__ __align__(16) __half  g_Vth  [(size_t)HB * 128 * 1024];
__device__ __align__(16) float   g_O    [(size_t)HB * S_SZ * D_V];
__device__ __align__(16) __half  g_Och  [(size_t)NTOK * 2048];
__device__ __align__(16) __half  g_Ocl  [(size_t)NTOK * 2048];
__device__ __align__(16) float   g_h1pre[(size_t)NTOK * D_M];
__device__ __align__(16) float   g_h1   [(size_t)NTOK * D_M];
__device__ __align__(16) __half  g_h1h  [(size_t)NTOK * D_M];
__device__ __align__(16) __half  g_h1l  [(size_t)NTOK * D_M];
__device__ __align__(16) __half  g_ffhh [(size_t)NTOK * HID];
__device__ __align__(16) __half  g_ffhl [(size_t)NTOK * HID];
__device__ __align__(16) float   g_r2pre[(size_t)NTOK * D_M];
__device__ float g_lamscale;

// ======================= lambda =======================
__global__ void lam_kernel(const float* __restrict__ lq1, const float* __restrict__ lk1,
                           const float* __restrict__ lq2, const float* __restrict__ lk2)
{
    __shared__ float s1[64], s2[64];
    int t = threadIdx.x;
    s1[t] = lq1[t] * lk1[t];
    s2[t] = lq2[t] * lk2[t];
    __syncthreads();
    if (t == 0) {
        float d1 = 0.f, d2 = 0.f;
        for (int i = 0; i < 64; i++) { d1 += s1[i]; d2 += s2[i]; }
        g_lamscale = 1.0f - (expf(d1) - expf(d2) + LAMBDA_INIT);
    }
}

// ======================= conversions =======================
// x -> fp16 hi/lo
__global__ void __launch_bounds__(256) conv_hilo_f16(
    const float* __restrict__ in, __half* __restrict__ oh, __half* __restrict__ ol, int n4)
{
    int i = blockIdx.x * 256 + threadIdx.x;
    if (i >= n4) return;
    float4 v = reinterpret_cast<const float4*>(in)[i];
    float vv[4] = {v.x, v.y, v.z, v.w};
    uint32_t fh[2], fl[2];
#pragma unroll
    for (int p = 0; p < 2; p++) {
        float a = vv[p * 2], b = vv[p * 2 + 1];
        float ha = __half2float(__float2half(a)), hb = __half2float(__float2half(b));
        fh[p] = packh2(a, b);
        fl[p] = packh2(a - ha, b - hb);
    }
    reinterpret_cast<uint32_t*>(oh)[i * 2] = fh[0];  reinterpret_cast<uint32_t*>(oh)[i * 2 + 1] = fh[1];
    reinterpret_cast<uint32_t*>(ol)[i * 2] = fl[0];  reinterpret_cast<uint32_t*>(ol)[i * 2 + 1] = fl[1];
}

// fused weight transpose-convert (all six weights in one launch)
// out[n][k] (K-major fp16 hi) from in[(n/dout)*K*dout + k*dout + n%dout]
__global__ void convW_all(
    const float* __restrict__ WQ1, const float* __restrict__ WK1, const float* __restrict__ WV,
    const float* __restrict__ WO,  const float* __restrict__ W1,  const float* __restrict__ W2,
    __half* __restrict__ bqh, __half* __restrict__ wvh, __half* __restrict__ woth,
    __half* __restrict__ w1th, __half* __restrict__ w2th)
{
    __shared__ float t[32][33];
    int lb = blockIdx.x;
    const float* in; __half* oh; int K, dout, gxm;
    if      (lb < 1024)  { in = WQ1; oh = bqh;                 K = 1024; dout = 64;   gxm = 32;  }
    else if (lb < 2048)  { in = WK1; oh = bqh + 1024 * 1024;   K = 1024; dout = 64;   gxm = 32;  lb -= 1024; }
    else if (lb < 4096)  { in = WV;  oh = wvh;                 K = 1024; dout = 128;  gxm = 32;  lb -= 2048; }
    else if (lb < 6144)  { in = WO;  oh = woth;                K = 2048; dout = 1024; gxm = 64;  lb -= 4096; }
    else if (lb < 10240) { in = W1;  oh = w1th;                K = 1024; dout = 4096; gxm = 32;  lb -= 6144; }
    else                 { in = W2;  oh = w2th;                K = 4096; dout = 1024; gxm = 128; lb -= 10240; }
    int gx = lb % gxm, gy = lb / gxm;
    int k0 = gx * 32, n0 = gy * 32;
    int h = n0 / dout, d0 = n0 - h * dout;
    const float* src = in + (size_t)h * K * dout + d0;
    for (int r = threadIdx.y; r < 32; r += 8)
        t[r][threadIdx.x] = src[(size_t)(k0 + r) * dout + threadIdx.x];
    __syncthreads();
    for (int r = threadIdx.y; r < 32; r += 8)
        oh[(size_t)(n0 + r) * K + k0 + threadIdx.x] = __float2half(t[threadIdx.x][r]);
}

// V transpose (fp16 hi): Vt[z][v][t] from Vh[(b*1024+t)*2048 + h*128 + v]
__global__ void convVt_f16(const __half* __restrict__ sh, __half* __restrict__ oh)
{
    __shared__ __half th[32][33];
    int z = blockIdx.z, h = z >> 2, b = z & 3;
    int t0 = blockIdx.x * 32, v0 = blockIdx.y * 32;
    for (int r = threadIdx.y; r < 32; r += 8)
        th[r][threadIdx.x] = sh[(size_t)(b * 1024 + t0 + r) * 2048 + h * 128 + v0 + threadIdx.x];
    __syncthreads();
    size_t base = (size_t)z * 131072;
    for (int r = threadIdx.y; r < 32; r += 8)
        oh[base + (size_t)(v0 + r) * 1024 + t0 + threadIdx.x] = th[threadIdx.x][r];
}

__global__ void concat_bias2(const float* __restrict__ bq, const float* __restrict__ bk,
                             float* __restrict__ o)
{
    int t = blockIdx.x * 256 + threadIdx.x;
    if (t < 1024) o[t] = bq[t];
    else if (t < 2048) o[t] = bk[t - 1024];
}

// ======================= tensor-core GEMM (fp16 mma.sync) ====================
// C[128x128 tile] = sum_k A[m][k]*B[n][k], K-major fp16.
// TERMS: 2 = Ah*Bh + Al*Bh ; 1 = Ah*Bh only.
// NS: cp.async pipeline depth. modes: 0 plain; 1 scores batched; 2 AV batched.
template<int TERMS, int NS>
__global__ void __launch_bounds__(256, 2) gemm_mma(
    const __half* __restrict__ Ah, const __half* __restrict__ Al,
    const __half* __restrict__ Bh,
    const float* __restrict__ bias, const float* __restrict__ res,
    float* __restrict__ cout, __half* __restrict__ outh, __half* __restrict__ outl,
    int K, int lda, int ldb, int ldc, float alpha, int relu, int mode)
{
    constexpr int NTILE = TERMS + 1;
    constexpr int STG = NTILE * 10240;
    constexpr uint32_t oAl = 10240;
    constexpr uint32_t oBh = (TERMS >= 2) ? 20480u : 10240u;
    extern __shared__ char dsm[];
    const int tid = threadIdx.x;
    const int lane = tid & 31, wid = tid >> 5;
    const int wy = wid >> 2, wx = wid & 3;       // warp tile: 64(M) x 32(N)
    const int m0 = blockIdx.y * 128, n0 = blockIdx.x * 128;
    const uint32_t smbase = smem_u32(dsm);

    size_t aoff = 0, boff = 0, coff = 0;
    if (mode == 1) {
        int z = blockIdx.z, h = z >> 2, b = z & 3;
        aoff = (size_t)(b << 10) * lda + (h << 6);
        boff = (size_t)(b << 10) * ldb + (h << 6);
        coff = (size_t)z << 20;
    } else if (mode == 2) {
        int z = blockIdx.z;
        aoff = (size_t)z << 20;
        boff = (size_t)z << 17;
        coff = (size_t)z << 17;
    }

    float acc[4][4][4];
#pragma unroll
    for (int i = 0; i < 4; i++)
#pragma unroll
        for (int j = 0; j < 4; j++)
#pragma unroll
            for (int q = 0; q < 4; q++) acc[i][j][q] = 0.f;

    const int niter = K >> 5;

    auto issue_tile = [&](int it, int slot) {
        int k0 = it << 5;
        uint32_t sb = smbase + slot * STG;
#pragma unroll
        for (int i = 0; i < 2; i++) {
            int l = tid + (i << 8);
            int row = l >> 2, c16 = l & 3;
            size_t aidx = aoff + (size_t)(m0 + row) * lda + k0 + (c16 << 3);
            size_t bidx = boff + (size_t)(n0 + row) * ldb + k0 + (c16 << 3);
            uint32_t so = (uint32_t)(row * 80 + (c16 << 4));
            CP_ASYNC16(sb + so,       Ah + aidx);
            if (TERMS >= 2) CP_ASYNC16(sb + oAl + so, Al + aidx);
            CP_ASYNC16(sb + oBh + so, Bh + bidx);
        }
        CP_COMMIT();
    };

#pragma unroll
    for (int s = 0; s < NS - 1; s++)
        if (s < niter) issue_tile(s, s);

    // ldmatrix per-lane addressing
    // A (x4): mats (m0-7,k0-7),(m8-15,k0-7),(m0-7,k8-15),(m8-15,k8-15)
    const int a_row = (wy << 6) + (lane & 7) + ((lane >> 3) & 1) * 8;  // + mt*16
    const int a_kb  = (lane >> 4) << 4;                                // + ks*32
    // B (x4): mats (n0-7,k0-7),(n0-7,k8-15),(n0-7,k16-23),(n0-7,k24-31)
    const int b_row8 = (wx << 5) + (lane & 7);                         // + nt*8
    const int b_k4   = ((lane >> 3) & 3) << 4;

    int cs = 0, is_ = NS - 1;
#pragma unroll 1
    for (int it = 0; it < niter; it++) {
        if (it + NS - 1 < niter) {
            issue_tile(it + NS - 1, is_);
            cp_waitg<NS - 1>();
        } else {
            cp_waitg<0>();
        }
        __syncthreads();

        uint32_t base = smbase + cs * STG;
        uint32_t pAh = base;
        uint32_t pAl = base + oAl;
        uint32_t pBh = base + oBh;

        // all B fragments for both k-steps in one x4 per nt
        uint32_t b4[4][4];
#pragma unroll
        for (int nt = 0; nt < 4; nt++) {
            uint32_t bo = (uint32_t)((b_row8 + (nt << 3)) * 80 + b_k4);
            ldmx4(b4[nt], pBh + bo);
        }

#pragma unroll
        for (int ks = 0; ks < 2; ks++) {
            const int ksb = ks << 5;
#pragma unroll
            for (int mt = 0; mt < 4; mt++) {
                uint32_t ao = (uint32_t)((a_row + (mt << 4)) * 80 + ksb + a_kb);
                uint32_t ahf[4], alf[4];
                ldmx4(ahf, pAh + ao);
                if (TERMS >= 2) ldmx4(alf, pAl + ao);
#pragma unroll
                for (int nt = 0; nt < 4; nt++) {
                    mma_f16(acc[mt][nt], ahf[0], ahf[1], ahf[2], ahf[3],
                            b4[nt][ks * 2], b4[nt][ks * 2 + 1]);
                    if (TERMS >= 2)
                        mma_f16(acc[mt][nt], alf[0], alf[1], alf[2], alf[3],
                                b4[nt][ks * 2], b4[nt][ks * 2 + 1]);
                }
            }
        }
        __syncthreads();
        cs = (cs + 1 == NS) ? 0 : cs + 1;
        is_ = (is_ + 1 == NS) ? 0 : is_ + 1;
    }

    // epilogue: alpha, bias, residual, relu; fp32 and/or fp16 hi(/lo) outputs
#pragma unroll
    for (int mt = 0; mt < 4; mt++) {
#pragma unroll
        for (int nt = 0; nt < 4; nt++) {
#pragma unroll
            for (int hf = 0; hf < 2; hf++) {
                int row = m0 + (wy << 6) + (mt << 4) + (lane >> 2) + (hf << 3);
                int col = n0 + (wx << 5) + (nt << 3) + ((lane & 3) << 1);
                float v0 = acc[mt][nt][hf * 2]     * alpha;
                float v1 = acc[mt][nt][hf * 2 + 1] * alpha;
                if (bias) { v0 += bias[col]; v1 += bias[col + 1]; }
                if (res) {
                    float2 rv = *reinterpret_cast<const float2*>(res + (size_t)row * ldc + col);
                    v0 += rv.x; v1 += rv.y;
                }
                if (relu) { v0 = fmaxf(v0, 0.f); v1 = fmaxf(v1, 0.f); }
                size_t oidx = coff + (size_t)row * ldc + col;
                if (cout) *reinterpret_cast<float2*>(cout + oidx) = make_float2(v0, v1);
                if (outh) {
                    *reinterpret_cast<uint32_t*>(outh + oidx) = packh2(v0, v1);
                    if (outl) {
                        float h0 = __half2float(__float2half(v0));
                        float h1 = __half2float(__float2half(v1));
                        *reinterpret_cast<uint32_t*>(outl + oidx) = packh2(v0 - h0, v1 - h1);
                    }
                }
            }
        }
    }
}

// ======================= softmax (fp16 scores in; fp32 A + fp16 hi out) =====
__global__ void __launch_bounds__(256) softmax_row(
    const __half* __restrict__ Sc, const int* __restrict__ mask, float* __restrict__ Aout,
    __half* __restrict__ Ahi)
{
    __shared__ float red[8];
    __shared__ float bcast;
    size_t row = blockIdx.x;
    int b = (int)((row >> 10) & 3);
    const __half* in = Sc + row * 1024;
    const int* mrow = mask + b * 1024;
    int t = threadIdx.x;
    int wid = t >> 5, lane = t & 31;

    float v[4];
    float mx = -INFINITY;
#pragma unroll
    for (int i = 0; i < 4; i++) {
        int c = t + i * 256;
        float val = __half2float(in[c]);
        if (mrow[c] == 0) val = -INFINITY;
        v[i] = val;
        mx = fmaxf(mx, val);
    }
#pragma unroll
    for (int o = 16; o; o >>= 1) mx = fmaxf(mx, __shfl_xor_sync(0xffffffffu, mx, o));
    if (lane == 0) red[wid] = mx;
    __syncthreads();
    if (t < 32) {
        float m2 = (t < 8) ? red[t] : -INFINITY;
#pragma unroll
        for (int o = 4; o; o >>= 1) m2 = fmaxf(m2, __shfl_xor_sync(0xffffffffu, m2, o));
        if (t == 0) bcast = m2;
    }
    __syncthreads();
    mx = bcast;

    float sum = 0.f;
#pragma unroll
    for (int i = 0; i < 4; i++) { v[i] = expf(v[i] - mx); sum += v[i]; }
#pragma unroll
    for (int o = 16; o; o >>= 1) sum += __shfl_xor_sync(0xffffffffu, sum, o);
    __syncthreads();
    if (lane == 0) red[wid] = sum;
    __syncthreads();
    if (t < 32) {
        float s2 = (t < 8) ? red[t] : 0.f;
#pragma unroll
        for (int o = 4; o; o >>= 1) s2 += __shfl_xor_sync(0xffffffffu, s2, o);
        if (t == 0) bcast = g_lamscale / s2;
    }
    __syncthreads();
    float sc = bcast;
#pragma unroll
    for (int i = 0; i < 4; i++) {
        size_t idx = row * 1024 + t + i * 256;
        float vv = v[i] * sc;
        Aout[idx] = vv;
        Ahi[idx] = __float2half(vv);
    }
}

// ======================= per-head LN(128) + concat, emits fp16 hi/lo ========
__global__ void __launch_bounds__(256) headln_kernel(
    const float* __restrict__ O, const float* __restrict__ w,
    const float* __restrict__ bvec, __half* __restrict__ och,
    __half* __restrict__ ocl)
{
    int gw = blockIdx.x * 8 + (threadIdx.x >> 5);
    int lane = threadIdx.x & 31;
    const float* xr = O + (size_t)gw * 128;
    float x0 = xr[lane], x1 = xr[lane + 32], x2 = xr[lane + 64], x3 = xr[lane + 96];
    float s = x0 + x1 + x2 + x3;
#pragma unroll
    for (int o = 16; o; o >>= 1) s += __shfl_xor_sync(0xffffffffu, s, o);
    float mean = s * (1.f / 128.f);
    float d0 = x0 - mean, d1 = x1 - mean, d2 = x2 - mean, d3 = x3 - mean;
    float q = d0 * d0 + d1 * d1 + d2 * d2 + d3 * d3;
#pragma unroll
    for (int o = 16; o; o >>= 1) q += __shfl_xor_sync(0xffffffffu, q, o);
    float rstd = rsqrtf(q * (1.f / 128.f) + 1e-5f);

    int z = gw >> 10, s_ = gw & 1023;
    int h = z >> 2, b = z & 3;
    size_t base = ((size_t)(b * S_SZ + s_)) * 2048 + h * 128;
    float vals[4] = {
        (d0 * rstd * w[lane]      + bvec[lane])      * HEADLN_SCALE,
        (d1 * rstd * w[lane + 32] + bvec[lane + 32]) * HEADLN_SCALE,
        (d2 * rstd * w[lane + 64] + bvec[lane + 64]) * HEADLN_SCALE,
        (d3 * rstd * w[lane + 96] + bvec[lane + 96]) * HEADLN_SCALE };
#pragma unroll
    for (int i = 0; i < 4; i++) {
        __half hi = __float2half(vals[i]);
        och[base + lane + i * 32] = hi;
        ocl[base + lane + i * 32] = __float2half(vals[i] - __half2float(hi));
    }
}

// ======================= LayerNorm 1024 (optional fp16 hi/lo out) ===========
__global__ void __launch_bounds__(256) ln1024(
    const float* __restrict__ X, const float* __restrict__ w,
    const float* __restrict__ bvec, float* __restrict__ out,
    __half* __restrict__ outh, __half* __restrict__ outl)
{
    __shared__ float red[8];
    __shared__ float bc;
    size_t row = blockIdx.x;
    const float* xr = X + row * 1024;
    int t = threadIdx.x;
    int wid = t >> 5, lane = t & 31;

    float v[4];
    float s = 0.f;
#pragma unroll
    for (int i = 0; i < 4; i++) { v[i] = xr[t + i * 256]; s += v[i]; }
#pragma unroll
    for (int o = 16; o; o >>= 1) s += __shfl_xor_sync(0xffffffffu, s, o);
    if (lane == 0) red[wid] = s;
    __syncthreads();
    if (t < 32) {
        float s2 = (t < 8) ? red[t] : 0.f;
#pragma unroll
        for (int o = 4; o; o >>= 1) s2 += __shfl_xor_sync(0xffffffffu, s2, o);
        if (t == 0) bc = s2 * (1.f / 1024.f);
    }
    __syncthreads();
    float mean = bc;

    float q = 0.f;
#pragma unroll
    for (int i = 0; i < 4; i++) { float d = v[i] - mean; q += d * d; }
#pragma unroll
    for (int o = 16; o; o >>= 1) q += __shfl_xor_sync(0xffffffffu, q, o);
    __syncthreads();
    if (lane == 0) red[wid] = q;
    __syncthreads();
    if (t < 32) {
        float q2 = (t < 8) ? red[t] : 0.f;
#pragma unroll
        for (int o = 4; o; o >>= 1) q2 += __shfl_xor_sync(0xffffffffu, q2, o);
        if (t == 0) bc = rsqrtf(q2 * (1.f / 1024.f) + 1e-5f);
    }
    __syncthreads();
    float rstd = bc;
#pragma unroll
    for (int i = 0; i < 4; i++) {
        int c = t + i * 256;
        float vv = (v[i] - mean) * rstd * w[c] + bvec[c];
        out[row * 1024 + c] = vv;
        if (outh) {
            __half hi = __float2half(vv);
            outh[row * 1024 + c] = hi;
            outl[row * 1024 + c] = __float2half(vv - __half2float(hi));
        }
    }
}

// ======================= host launcher ======================================
extern "C" void kernel_launch(void* const* d_in, const int* in_sizes, int n_in,
                              void* d_out, int out_size)
{
    const float* x    = (const float*)d_in[0];
    const int*   mask = (const int*)  d_in[1];
    const float* WQ1  = (const float*)d_in[2];
    const float* bQ1  = (const float*)d_in[3];
    const float* WK1  = (const float*)d_in[4];
    const float* bK1  = (const float*)d_in[5];
    const float* WV   = (const float*)d_in[6];
    const float* bV   = (const float*)d_in[7];
    const float* lnhw = (const float*)d_in[8];
    const float* lnhb = (const float*)d_in[9];
    const float* WO   = (const float*)d_in[10];
    const float* bO   = (const float*)d_in[11];
    const float* ln1w = (const float*)d_in[12];
    const float* ln1b = (const float*)d_in[13];
    const float* ln2w = (const float*)d_in[14];
    const float* ln2b = (const float*)d_in[15];
    const float* W1   = (const float*)d_in[16];
    const float* b1   = (const float*)d_in[17];
    const float* W2   = (const float*)d_in[18];
    const float* b2   = (const float*)d_in[19];
    const float* lq1  = (const float*)d_in[20];
    const float* lk1  = (const float*)d_in[21];
    const float* lq2  = (const float*)d_in[22];
    const float* lk2  = (const float*)d_in[23];

    float* out = (float*)d_out;

    const int SM2 = 3 * 3 * 10240;   // 92160: 2-term, 3-stage
    const int SM1 = 4 * 2 * 10240;   // 81920: 1-term, 4-stage
    cudaFuncSetAttribute(gemm_mma<2, 3>, cudaFuncAttributeMaxDynamicSharedMemorySize, SM2);
    cudaFuncSetAttribute(gemm_mma<1, 4>, cudaFuncAttributeMaxDynamicSharedMemorySize, SM1);

    float *op, *h1pre, *h1, *r2pre, *biasqk;
    __half *qkh, *qkl, *bqh, *wvh, *woth, *w1th, *w2th;
    __half *xhf, *xlf, *sh, *ah, *vh, *vth, *och, *ocl, *h1h, *h1l, *ffhh, *ffhl;
    cudaGetSymbolAddress((void**)&qkh,   g_QKh);
    cudaGetSymbolAddress((void**)&qkl,   g_QKl);
    cudaGetSymbolAddress((void**)&bqh,   g_Bqh);
    cudaGetSymbolAddress((void**)&wvh,   g_WVh);
    cudaGetSymbolAddress((void**)&woth,  g_WOth);
    cudaGetSymbolAddress((void**)&w1th,  g_W1th);
    cudaGetSymbolAddress((void**)&w2th,  g_W2th);
    cudaGetSymbolAddress((void**)&biasqk, g_biasqk);
    cudaGetSymbolAddress((void**)&xhf,   g_xhf);
    cudaGetSymbolAddress((void**)&xlf,   g_xlf);
    cudaGetSymbolAddress((void**)&sh,    g_Sh);
    cudaGetSymbolAddress((void**)&ah,    g_Ah);
    cudaGetSymbolAddress((void**)&vh,    g_Vh);
    cudaGetSymbolAddress((void**)&vth,   g_Vth);
    cudaGetSymbolAddress((void**)&op,    g_O);
    cudaGetSymbolAddress((void**)&och,   g_Och);
    cudaGetSymbolAddress((void**)&ocl,   g_Ocl);
    cudaGetSymbolAddress((void**)&h1pre, g_h1pre);
    cudaGetSymbolAddress((void**)&h1,    g_h1);
    cudaGetSymbolAddress((void**)&h1h,   g_h1h);
    cudaGetSymbolAddress((void**)&h1l,   g_h1l);
    cudaGetSymbolAddress((void**)&ffhh,  g_ffhh);
    cudaGetSymbolAddress((void**)&ffhl,  g_ffhl);
    cudaGetSymbolAddress((void**)&r2pre, g_r2pre);

    float* A_ptr = (out_size >= FULL_ELEMS) ? (out + R2_ELEMS) : op;  // fp32 A dest

    // launch order arranged so ncu (-s 5 -c 1) captures a GEMM (6th launch)
    lam_kernel<<<1, 64>>>(lq1, lk1, lq2, lk2);                               // 1
    concat_bias2<<<8, 256>>>(bQ1, bK1, biasqk);                              // 2
    convW_all<<<14336, dim3(32, 8)>>>(WQ1, WK1, WV, WO, W1, W2,
                                      bqh, wvh, woth, w1th, w2th);           // 3
    conv_hilo_f16<<<4096, 256>>>(x, xhf, xlf, 1048576);                      // 4

    // QK projection (fp16 2-term): [4096, 2048], K=1024; emits hi+lo
    gemm_mma<2, 3><<<dim3(16, 32, 1), 256, SM2>>>(
        xhf, xlf, bqh, biasqk, nullptr, nullptr, qkh, qkl,
        1024, 1024, 1024, 2048, 1.0f, 0, 0);                                 // 5

    // V projection (fp16 2-term): [4096, 2048], K=1024, hi only
    gemm_mma<2, 3><<<dim3(16, 32, 1), 256, SM2>>>(
        xhf, xlf, wvh, bV, nullptr, nullptr, vh, nullptr,
        1024, 1024, 1024, 2048, 1.0f, 0, 0);                                 // 6 <- profiled

    // scores (fp16 2-term, Q hi/lo x K hi), batched; alpha = 1/sqrt(1024); fp16 out
    gemm_mma<2, 3><<<dim3(8, 8, 64), 256, SM2>>>(
        qkh, qkl, qkh + 1024, nullptr, nullptr, nullptr, sh, nullptr,
        64, 2048, 2048, 1024, 0.03125f, 0, 1);

    softmax_row<<<65536, 256>>>(sh, mask, A_ptr, ah);
    convVt_f16<<<dim3(32, 4, 64), dim3(32, 8)>>>(vh, vth);

    // AV (fp16 1-term), batched
    gemm_mma<1, 4><<<dim3(1, 8, 64), 256, SM1>>>(
        ah, nullptr, vth, nullptr, nullptr, op, nullptr, nullptr,
        1024, 1024, 1024, 128, 1.0f, 0, 2);

    headln_kernel<<<8192, 256>>>(op, lnhw, lnhb, och, ocl);

    // output projection (fp16 2-term) + residual(x), LN1
    gemm_mma<2, 3><<<dim3(8, 32, 1), 256, SM2>>>(
        och, ocl, woth, bO, x, h1pre, nullptr, nullptr,
        2048, 2048, 2048, 1024, 1.0f, 0, 0);
    ln1024<<<4096, 256>>>(h1pre, ln1w, ln1b, h1, h1h, h1l);

    // FFN (fp16 2-term): relu(h1 @ W1 + b1) @ W2 + b2 + h1, LN2 -> out
    gemm_mma<2, 3><<<dim3(32, 32, 1), 256, SM2>>>(
        h1h, h1l, w1th, b1, nullptr, nullptr, ffhh, ffhl,
        1024, 1024, 1024, 4096, 1.0f, 1, 0);
    gemm_mma<2, 3><<<dim3(8, 32, 1), 256, SM2>>>(
        ffhh, ffhl, w2th, b2, h1, r2pre, nullptr, nullptr,
        4096, 4096, 4096, 1024, 1.0f, 0, 0);
    ln1024<<<4096, 256>>>(r2pre, ln2w, ln2b, out, nullptr, nullptr);
}

// round 14
// speedup vs baseline: 1.4303x; 1.1709x over previous
#include <cuda_runtime.h>
#include <cuda_fp16.h>
#include <math.h>
#include <stddef.h>
#include <stdint.h>

#define B_SZ   4
#define S_SZ   1024
#define D_M    1024
#define H_N    16
#define D_INT  64
#define D_V    128
#define HID    4096
#define NTOK   4096
#define HB     64
#define LAMBDA_INIT 0.3555090675909693f
#define HEADLN_SCALE 0.6444909324090307f
#define R2_ELEMS 4194304
#define FULL_ELEMS 71303168

// ======================= helpers =======================
__device__ __forceinline__ uint32_t smem_u32(const void* p) {
    uint32_t a;
    asm("{ .reg .u64 t; cvta.to.shared.u64 t, %1; cvt.u32.u64 %0, t; }" : "=r"(a) : "l"(p));
    return a;
}
#define CP_ASYNC16(sdst, gsrc) \
    asm volatile("cp.async.cg.shared.global [%0], [%1], 16;" :: "r"(sdst), "l"(gsrc) : "memory")
#define CP_COMMIT() asm volatile("cp.async.commit_group;" ::: "memory")
template<int N> __device__ __forceinline__ void cp_waitg() {
    asm volatile("cp.async.wait_group %0;" :: "n"(N) : "memory");
}

__device__ __forceinline__ void mma_f16(float* d, uint32_t a0, uint32_t a1, uint32_t a2,
                                        uint32_t a3, uint32_t b0, uint32_t b1) {
    asm volatile(
        "mma.sync.aligned.m16n8k16.row.col.f32.f16.f16.f32 "
        "{%0,%1,%2,%3}, {%4,%5,%6,%7}, {%8,%9}, {%0,%1,%2,%3};"
        : "+f"(d[0]), "+f"(d[1]), "+f"(d[2]), "+f"(d[3])
        : "r"(a0), "r"(a1), "r"(a2), "r"(a3), "r"(b0), "r"(b1));
}
__device__ __forceinline__ void ldmx4(uint32_t* r, uint32_t addr) {
    asm volatile("ldmatrix.sync.aligned.m8n8.x4.shared.b16 {%0,%1,%2,%3}, [%4];"
        : "=r"(r[0]), "=r"(r[1]), "=r"(r[2]), "=r"(r[3]) : "r"(addr));
}
__device__ __forceinline__ uint32_t packh2(float a, float b) {
    __half2 p; p.x = __float2half(a); p.y = __float2half(b);
    return *reinterpret_cast<uint32_t*>(&p);
}

// ======================= static scratch =======================
__device__ __align__(16) __half  g_QKh  [(size_t)NTOK * 2048];   // Q|K fp16 hi
__device__ __align__(16) __half  g_QKl  [(size_t)NTOK * 2048];   // Q|K fp16 lo
__device__ __align__(16) __half  g_Bqh  [(size_t)2048 * 1024];   // WQ|WK K-major fp16 hi
__device__ __align__(16) __half  g_WVh  [(size_t)2048 * 1024];
__device__ __align__(16) __half  g_WOth [(size_t)1024 * 2048];
__device__ __align__(16) __half  g_W1th [(size_t)4096 * 1024];
__device__ __align__(16) __half  g_W2th [(size_t)1024 * 4096];
__device__ __align__(16) float   g_biasqk[2048];
__device__ __align__(16) __half  g_xhf  [(size_t)NTOK * 1024];
__device__ __align__(16) __half  g_xlf  [(size_t)NTOK * 1024];
__device__ __align__(16) __half  g_Ah   [(size_t)HB * S_SZ * S_SZ];  // unnormalized exp, fp16
__device__ __align__(16) float   g_part [(size_t)HB * 8 * 8 * 128];  // per-CTA row partial sums
__device__ __align__(16) __half  g_Vh   [(size_t)NTOK * 2048];
__device__ __align__(16) __half  g_Vth  [(size_t)HB * 128 * 1024];
__device__ __align__(16) float   g_O    [(size_t)HB * S_SZ * D_V];
__device__ __align__(16) __half  g_Och  [(size_t)NTOK * 2048];
__device__ __align__(16) __half  g_Ocl  [(size_t)NTOK * 2048];
__device__ __align__(16) float   g_h1pre[(size_t)NTOK * D_M];
__device__ __align__(16) float   g_h1   [(size_t)NTOK * D_M];
__device__ __align__(16) __half  g_h1h  [(size_t)NTOK * D_M];
__device__ __align__(16) __half  g_h1l  [(size_t)NTOK * D_M];
__device__ __align__(16) __half  g_ffhh [(size_t)NTOK * HID];
__device__ __align__(16) float   g_r2pre[(size_t)NTOK * D_M];
__device__ float g_lamscale;

// ======================= lambda =======================
__global__ void lam_kernel(const float* __restrict__ lq1, const float* __restrict__ lk1,
                           const float* __restrict__ lq2, const float* __restrict__ lk2)
{
    __shared__ float s1[64], s2[64];
    int t = threadIdx.x;
    s1[t] = lq1[t] * lk1[t];
    s2[t] = lq2[t] * lk2[t];
    __syncthreads();
    if (t == 0) {
        float d1 = 0.f, d2 = 0.f;
        for (int i = 0; i < 64; i++) { d1 += s1[i]; d2 += s2[i]; }
        g_lamscale = 1.0f - (expf(d1) - expf(d2) + LAMBDA_INIT);
    }
}

// ======================= conversions =======================
__global__ void __launch_bounds__(256) conv_hilo_f16(
    const float* __restrict__ in, __half* __restrict__ oh, __half* __restrict__ ol, int n4)
{
    int i = blockIdx.x * 256 + threadIdx.x;
    if (i >= n4) return;
    float4 v = reinterpret_cast<const float4*>(in)[i];
    float vv[4] = {v.x, v.y, v.z, v.w};
    uint32_t fh[2], fl[2];
#pragma unroll
    for (int p = 0; p < 2; p++) {
        float a = vv[p * 2], b = vv[p * 2 + 1];
        float ha = __half2float(__float2half(a)), hb = __half2float(__float2half(b));
        fh[p] = packh2(a, b);
        fl[p] = packh2(a - ha, b - hb);
    }
    reinterpret_cast<uint32_t*>(oh)[i * 2] = fh[0];  reinterpret_cast<uint32_t*>(oh)[i * 2 + 1] = fh[1];
    reinterpret_cast<uint32_t*>(ol)[i * 2] = fl[0];  reinterpret_cast<uint32_t*>(ol)[i * 2 + 1] = fl[1];
}

// fused weight transpose-convert (all six weights in one launch)
__global__ void convW_all(
    const float* __restrict__ WQ1, const float* __restrict__ WK1, const float* __restrict__ WV,
    const float* __restrict__ WO,  const float* __restrict__ W1,  const float* __restrict__ W2,
    __half* __restrict__ bqh, __half* __restrict__ wvh, __half* __restrict__ woth,
    __half* __restrict__ w1th, __half* __restrict__ w2th)
{
    __shared__ float t[32][33];
    int lb = blockIdx.x;
    const float* in; __half* oh; int K, dout, gxm;
    if      (lb < 1024)  { in = WQ1; oh = bqh;                 K = 1024; dout = 64;   gxm = 32;  }
    else if (lb < 2048)  { in = WK1; oh = bqh + 1024 * 1024;   K = 1024; dout = 64;   gxm = 32;  lb -= 1024; }
    else if (lb < 4096)  { in = WV;  oh = wvh;                 K = 1024; dout = 128;  gxm = 32;  lb -= 2048; }
    else if (lb < 6144)  { in = WO;  oh = woth;                K = 2048; dout = 1024; gxm = 64;  lb -= 4096; }
    else if (lb < 10240) { in = W1;  oh = w1th;                K = 1024; dout = 4096; gxm = 32;  lb -= 6144; }
    else                 { in = W2;  oh = w2th;                K = 4096; dout = 1024; gxm = 128; lb -= 10240; }
    int gx = lb % gxm, gy = lb / gxm;
    int k0 = gx * 32, n0 = gy * 32;
    int h = n0 / dout, d0 = n0 - h * dout;
    const float* src = in + (size_t)h * K * dout + d0;
    for (int r = threadIdx.y; r < 32; r += 8)
        t[r][threadIdx.x] = src[(size_t)(k0 + r) * dout + threadIdx.x];
    __syncthreads();
    for (int r = threadIdx.y; r < 32; r += 8)
        oh[(size_t)(n0 + r) * K + k0 + threadIdx.x] = __float2half(t[threadIdx.x][r]);
}

// V transpose (fp16 hi)
__global__ void convVt_f16(const __half* __restrict__ sh, __half* __restrict__ oh)
{
    __shared__ __half th[32][33];
    int z = blockIdx.z, h = z >> 2, b = z & 3;
    int t0 = blockIdx.x * 32, v0 = blockIdx.y * 32;
    for (int r = threadIdx.y; r < 32; r += 8)
        th[r][threadIdx.x] = sh[(size_t)(b * 1024 + t0 + r) * 2048 + h * 128 + v0 + threadIdx.x];
    __syncthreads();
    size_t base = (size_t)z * 131072;
    for (int r = threadIdx.y; r < 32; r += 8)
        oh[base + (size_t)(v0 + r) * 1024 + t0 + threadIdx.x] = th[threadIdx.x][r];
}

__global__ void concat_bias2(const float* __restrict__ bq, const float* __restrict__ bk,
                             float* __restrict__ o)
{
    int t = blockIdx.x * 256 + threadIdx.x;
    if (t < 1024) o[t] = bq[t];
    else if (t < 2048) o[t] = bk[t - 1024];
}

// ======================= tensor-core GEMM (fp16 mma.sync) ====================
// MODE 0: plain GEMM. MODE 1: scores, fused exp epilogue (writes e fp16 + row
// partial sums; mask applied). MODE 2: AV batched.
template<int TERMS, int NS, int MODE>
__global__ void __launch_bounds__(256, 2) gemm_mma(
    const __half* __restrict__ Ah, const __half* __restrict__ Al,
    const __half* __restrict__ Bh,
    const float* __restrict__ bias, const float* __restrict__ res,
    float* __restrict__ cout, __half* __restrict__ outh, __half* __restrict__ outl,
    float* __restrict__ partial, const int* __restrict__ mask,
    int K, int lda, int ldb, int ldc, float alpha, int relu)
{
    constexpr int NTILE = TERMS + 1;
    constexpr int STG = NTILE * 10240;
    constexpr uint32_t oAl = 10240;
    constexpr uint32_t oBh = (TERMS >= 2) ? 20480u : 10240u;
    extern __shared__ char dsm[];
    const int tid = threadIdx.x;
    const int lane = tid & 31, wid = tid >> 5;
    const int wy = wid >> 2, wx = wid & 3;       // warp tile: 64(M) x 32(N)
    const int m0 = blockIdx.y * 128, n0 = blockIdx.x * 128;
    const uint32_t smbase = smem_u32(dsm);

    size_t aoff = 0, boff = 0, coff = 0;
    if (MODE == 1) {
        int z = blockIdx.z, h = z >> 2, b = z & 3;
        aoff = (size_t)(b << 10) * lda + (h << 6);
        boff = (size_t)(b << 10) * ldb + (h << 6);
        coff = (size_t)z << 20;
    } else if (MODE == 2) {
        int z = blockIdx.z;
        aoff = (size_t)z << 20;
        boff = (size_t)z << 17;
        coff = (size_t)z << 17;
    }

    float acc[4][4][4];
#pragma unroll
    for (int i = 0; i < 4; i++)
#pragma unroll
        for (int j = 0; j < 4; j++)
#pragma unroll
            for (int q = 0; q < 4; q++) acc[i][j][q] = 0.f;

    const int niter = K >> 5;

    auto issue_tile = [&](int it, int slot) {
        int k0 = it << 5;
        uint32_t sb = smbase + slot * STG;
#pragma unroll
        for (int i = 0; i < 2; i++) {
            int l = tid + (i << 8);
            int row = l >> 2, c16 = l & 3;
            size_t aidx = aoff + (size_t)(m0 + row) * lda + k0 + (c16 << 3);
            size_t bidx = boff + (size_t)(n0 + row) * ldb + k0 + (c16 << 3);
            uint32_t so = (uint32_t)(row * 80 + (c16 << 4));
            CP_ASYNC16(sb + so,       Ah + aidx);
            if (TERMS >= 2) CP_ASYNC16(sb + oAl + so, Al + aidx);
            CP_ASYNC16(sb + oBh + so, Bh + bidx);
        }
        CP_COMMIT();
    };

#pragma unroll
    for (int s = 0; s < NS - 1; s++)
        if (s < niter) issue_tile(s, s);

    // ldmatrix per-lane addressing
    const int a_row = (wy << 6) + (lane & 7) + ((lane >> 3) & 1) * 8;  // + mt*16
    const int a_kb  = (lane >> 4) << 4;                                // + ks*32
    const int b_row8 = (wx << 5) + (lane & 7);                         // + nt*8
    const int b_k4   = ((lane >> 3) & 3) << 4;

    int cs = 0, is_ = NS - 1;
#pragma unroll 1
    for (int it = 0; it < niter; it++) {
        if (it + NS - 1 < niter) {
            issue_tile(it + NS - 1, is_);
            cp_waitg<NS - 1>();
        } else {
            cp_waitg<0>();
        }
        __syncthreads();

        uint32_t base = smbase + cs * STG;
        uint32_t pAh = base;
        uint32_t pAl = base + oAl;
        uint32_t pBh = base + oBh;

        uint32_t b4[4][4];
#pragma unroll
        for (int nt = 0; nt < 4; nt++) {
            uint32_t bo = (uint32_t)((b_row8 + (nt << 3)) * 80 + b_k4);
            ldmx4(b4[nt], pBh + bo);
        }

#pragma unroll
        for (int ks = 0; ks < 2; ks++) {
            const int ksb = ks << 5;
#pragma unroll
            for (int mt = 0; mt < 4; mt++) {
                uint32_t ao = (uint32_t)((a_row + (mt << 4)) * 80 + ksb + a_kb);
                uint32_t ahf[4], alf[4];
                ldmx4(ahf, pAh + ao);
                if (TERMS >= 2) ldmx4(alf, pAl + ao);
#pragma unroll
                for (int nt = 0; nt < 4; nt++) {
                    mma_f16(acc[mt][nt], ahf[0], ahf[1], ahf[2], ahf[3],
                            b4[nt][ks * 2], b4[nt][ks * 2 + 1]);
                    if (TERMS >= 2)
                        mma_f16(acc[mt][nt], alf[0], alf[1], alf[2], alf[3],
                                b4[nt][ks * 2], b4[nt][ks * 2 + 1]);
                }
            }
        }
        __syncthreads();
        cs = (cs + 1 == NS) ? 0 : cs + 1;
        is_ = (is_ + 1 == NS) ? 0 : is_ + 1;
    }

    if (MODE == 1) {
        // fused exp + row-partial-sum epilogue (scores). No max subtraction:
        // |scores| < 1 by construction, exp is safe.
        const int b = blockIdx.z & 3;
        const int* mrow = mask + (b << 10) + n0;
        float rowacc[4][2];
#pragma unroll
        for (int mt = 0; mt < 4; mt++) { rowacc[mt][0] = 0.f; rowacc[mt][1] = 0.f; }
#pragma unroll
        for (int mt = 0; mt < 4; mt++) {
#pragma unroll
            for (int hf = 0; hf < 2; hf++) {
                int row = m0 + (mt << 4) + (wy << 6) + (lane >> 2) + (hf << 3);
                float rsum = 0.f;
#pragma unroll
                for (int nt = 0; nt < 4; nt++) {
                    int cl = (wx << 5) + (nt << 3) + ((lane & 3) << 1);
                    float e0 = mrow[cl]     ? __expf(acc[mt][nt][hf * 2]     * alpha) : 0.f;
                    float e1 = mrow[cl + 1] ? __expf(acc[mt][nt][hf * 2 + 1] * alpha) : 0.f;
                    rsum += e0 + e1;
                    *reinterpret_cast<uint32_t*>(outh + coff + (size_t)row * 1024 + n0 + cl)
                        = packh2(e0, e1);
                }
                rowacc[mt][hf] += rsum;
            }
        }
        float (*rs)[4] = reinterpret_cast<float(*)[4]>(dsm);
#pragma unroll
        for (int mt = 0; mt < 4; mt++)
#pragma unroll
            for (int hf = 0; hf < 2; hf++) {
                float v = rowacc[mt][hf];
                v += __shfl_xor_sync(0xffffffffu, v, 1);
                v += __shfl_xor_sync(0xffffffffu, v, 2);
                if ((lane & 3) == 0) {
                    int rl = (wy << 6) + (mt << 4) + (lane >> 2) + (hf << 3);
                    rs[rl][wx] = v;
                }
            }
        __syncthreads();
        if (tid < 128) {
            float s4 = rs[tid][0] + rs[tid][1] + rs[tid][2] + rs[tid][3];
            partial[(((size_t)blockIdx.z << 6) + (blockIdx.y << 3) + blockIdx.x) * 128 + tid] = s4;
        }
        return;
    }

    // generic epilogue
#pragma unroll
    for (int mt = 0; mt < 4; mt++) {
#pragma unroll
        for (int nt = 0; nt < 4; nt++) {
#pragma unroll
            for (int hf = 0; hf < 2; hf++) {
                int row = m0 + (wy << 6) + (mt << 4) + (lane >> 2) + (hf << 3);
                int col = n0 + (wx << 5) + (nt << 3) + ((lane & 3) << 1);
                float v0 = acc[mt][nt][hf * 2]     * alpha;
                float v1 = acc[mt][nt][hf * 2 + 1] * alpha;
                if (bias) { v0 += bias[col]; v1 += bias[col + 1]; }
                if (res) {
                    float2 rv = *reinterpret_cast<const float2*>(res + (size_t)row * ldc + col);
                    v0 += rv.x; v1 += rv.y;
                }
                if (relu) { v0 = fmaxf(v0, 0.f); v1 = fmaxf(v1, 0.f); }
                size_t oidx = coff + (size_t)row * ldc + col;
                if (cout) *reinterpret_cast<float2*>(cout + oidx) = make_float2(v0, v1);
                if (outh) {
                    *reinterpret_cast<uint32_t*>(outh + oidx) = packh2(v0, v1);
                    if (outl) {
                        float h0 = __half2float(__float2half(v0));
                        float h1 = __half2float(__float2half(v1));
                        *reinterpret_cast<uint32_t*>(outl + oidx) = packh2(v0 - h0, v1 - h1);
                    }
                }
            }
        }
    }
}

// ======================= A normalization: A = e * lamscale/rowsum (fp32) ====
__global__ void __launch_bounds__(256) anorm_kernel(
    const __half* __restrict__ e, const float* __restrict__ partial, float* __restrict__ A)
{
    size_t row = blockIdx.x;
    int z = (int)(row >> 10), s = (int)(row & 1023);
    size_t base = (((size_t)(z << 6) + ((s >> 7) << 3)) << 7) + (s & 127);
    float sum = 0.f;
#pragma unroll
    for (int nb = 0; nb < 8; nb++) sum += partial[base + (nb << 7)];
    float sc = g_lamscale / sum;
    int t = threadIdx.x;
#pragma unroll
    for (int i = 0; i < 2; i++) {
        int c = (t + (i << 8)) << 1;
        __half2 p = *reinterpret_cast<const __half2*>(e + row * 1024 + c);
        float2 o = make_float2(__half2float(p.x) * sc, __half2float(p.y) * sc);
        *reinterpret_cast<float2*>(A + row * 1024 + c) = o;
    }
}

// ======================= per-head LN(128) + concat (normalizes O rows) ======
__global__ void __launch_bounds__(256) headln_kernel(
    const float* __restrict__ O, const float* __restrict__ partial,
    const float* __restrict__ w, const float* __restrict__ bvec,
    __half* __restrict__ och, __half* __restrict__ ocl)
{
    int gw = blockIdx.x * 8 + (threadIdx.x >> 5);
    int lane = threadIdx.x & 31;
    int z = gw >> 10, s_ = gw & 1023;
    size_t pbase = (((size_t)(z << 6) + ((s_ >> 7) << 3)) << 7) + (s_ & 127);
    float sum = 0.f;
#pragma unroll
    for (int nb = 0; nb < 8; nb++) sum += partial[pbase + (nb << 7)];
    float sc = g_lamscale / sum;   // exact row normalization of unscaled O

    const float* xr = O + (size_t)gw * 128;
    float x0 = xr[lane] * sc, x1 = xr[lane + 32] * sc,
          x2 = xr[lane + 64] * sc, x3 = xr[lane + 96] * sc;
    float s = x0 + x1 + x2 + x3;
#pragma unroll
    for (int o = 16; o; o >>= 1) s += __shfl_xor_sync(0xffffffffu, s, o);
    float mean = s * (1.f / 128.f);
    float d0 = x0 - mean, d1 = x1 - mean, d2 = x2 - mean, d3 = x3 - mean;
    float q = d0 * d0 + d1 * d1 + d2 * d2 + d3 * d3;
#pragma unroll
    for (int o = 16; o; o >>= 1) q += __shfl_xor_sync(0xffffffffu, q, o);
    float rstd = rsqrtf(q * (1.f / 128.f) + 1e-5f);

    int h = z >> 2, b = z & 3;
    size_t base = ((size_t)(b * S_SZ + s_)) * 2048 + h * 128;
    float vals[4] = {
        (d0 * rstd * w[lane]      + bvec[lane])      * HEADLN_SCALE,
        (d1 * rstd * w[lane + 32] + bvec[lane + 32]) * HEADLN_SCALE,
        (d2 * rstd * w[lane + 64] + bvec[lane + 64]) * HEADLN_SCALE,
        (d3 * rstd * w[lane + 96] + bvec[lane + 96]) * HEADLN_SCALE };
#pragma unroll
    for (int i = 0; i < 4; i++) {
        __half hi = __float2half(vals[i]);
        och[base + lane + i * 32] = hi;
        ocl[base + lane + i * 32] = __float2half(vals[i] - __half2float(hi));
    }
}

// ======================= LayerNorm 1024 (optional fp16 hi/lo out) ===========
__global__ void __launch_bounds__(256) ln1024(
    const float* __restrict__ X, const float* __restrict__ w,
    const float* __restrict__ bvec, float* __restrict__ out,
    __half* __restrict__ outh, __half* __restrict__ outl)
{
    __shared__ float red[8];
    __shared__ float bc;
    size_t row = blockIdx.x;
    const float* xr = X + row * 1024;
    int t = threadIdx.x;
    int wid = t >> 5, lane = t & 31;

    float v[4];
    float s = 0.f;
#pragma unroll
    for (int i = 0; i < 4; i++) { v[i] = xr[t + i * 256]; s += v[i]; }
#pragma unroll
    for (int o = 16; o; o >>= 1) s += __shfl_xor_sync(0xffffffffu, s, o);
    if (lane == 0) red[wid] = s;
    __syncthreads();
    if (t < 32) {
        float s2 = (t < 8) ? red[t] : 0.f;
#pragma unroll
        for (int o = 4; o; o >>= 1) s2 += __shfl_xor_sync(0xffffffffu, s2, o);
        if (t == 0) bc = s2 * (1.f / 1024.f);
    }
    __syncthreads();
    float mean = bc;

    float q = 0.f;
#pragma unroll
    for (int i = 0; i < 4; i++) { float d = v[i] - mean; q += d * d; }
#pragma unroll
    for (int o = 16; o; o >>= 1) q += __shfl_xor_sync(0xffffffffu, q, o);
    __syncthreads();
    if (lane == 0) red[wid] = q;
    __syncthreads();
    if (t < 32) {
        float q2 = (t < 8) ? red[t] : 0.f;
#pragma unroll
        for (int o = 4; o; o >>= 1) q2 += __shfl_xor_sync(0xffffffffu, q2, o);
        if (t == 0) bc = rsqrtf(q2 * (1.f / 1024.f) + 1e-5f);
    }
    __syncthreads();
    float rstd = bc;
#pragma unroll
    for (int i = 0; i < 4; i++) {
        int c = t + i * 256;
        float vv = (v[i] - mean) * rstd * w[c] + bvec[c];
        out[row * 1024 + c] = vv;
        if (outh) {
            __half hi = __float2half(vv);
            outh[row * 1024 + c] = hi;
            if (outl) outl[row * 1024 + c] = __float2half(vv - __half2float(hi));
        }
    }
}

// ======================= host launcher ======================================
extern "C" void kernel_launch(void* const* d_in, const int* in_sizes, int n_in,
                              void* d_out, int out_size)
{
    const float* x    = (const float*)d_in[0];
    const int*   mask = (const int*)  d_in[1];
    const float* WQ1  = (const float*)d_in[2];
    const float* bQ1  = (const float*)d_in[3];
    const float* WK1  = (const float*)d_in[4];
    const float* bK1  = (const float*)d_in[5];
    const float* WV   = (const float*)d_in[6];
    const float* bV   = (const float*)d_in[7];
    const float* lnhw = (const float*)d_in[8];
    const float* lnhb = (const float*)d_in[9];
    const float* WO   = (const float*)d_in[10];
    const float* bO   = (const float*)d_in[11];
    const float* ln1w = (const float*)d_in[12];
    const float* ln1b = (const float*)d_in[13];
    const float* ln2w = (const float*)d_in[14];
    const float* ln2b = (const float*)d_in[15];
    const float* W1   = (const float*)d_in[16];
    const float* b1   = (const float*)d_in[17];
    const float* W2   = (const float*)d_in[18];
    const float* b2   = (const float*)d_in[19];
    const float* lq1  = (const float*)d_in[20];
    const float* lk1  = (const float*)d_in[21];
    const float* lq2  = (const float*)d_in[22];
    const float* lk2  = (const float*)d_in[23];

    float* out = (float*)d_out;

    const int SM2 = 3 * 3 * 10240;   // 92160: 2-term, 3-stage
    const int SM1 = 4 * 2 * 10240;   // 81920: 1-term, 4-stage
    const int SM1b = 3 * 2 * 10240;  // 61440: 1-term, 3-stage
    cudaFuncSetAttribute(gemm_mma<2, 3, 0>, cudaFuncAttributeMaxDynamicSharedMemorySize, SM2);
    cudaFuncSetAttribute(gemm_mma<2, 3, 1>, cudaFuncAttributeMaxDynamicSharedMemorySize, SM2);
    cudaFuncSetAttribute(gemm_mma<1, 4, 2>, cudaFuncAttributeMaxDynamicSharedMemorySize, SM1);
    cudaFuncSetAttribute(gemm_mma<1, 3, 0>, cudaFuncAttributeMaxDynamicSharedMemorySize, SM1b);

    float *op, *h1pre, *h1, *r2pre, *biasqk, *part;
    __half *qkh, *qkl, *bqh, *wvh, *woth, *w1th, *w2th;
    __half *xhf, *xlf, *ah, *vh, *vth, *och, *ocl, *h1h, *h1l, *ffhh;
    cudaGetSymbolAddress((void**)&qkh,   g_QKh);
    cudaGetSymbolAddress((void**)&qkl,   g_QKl);
    cudaGetSymbolAddress((void**)&bqh,   g_Bqh);
    cudaGetSymbolAddress((void**)&wvh,   g_WVh);
    cudaGetSymbolAddress((void**)&woth,  g_WOth);
    cudaGetSymbolAddress((void**)&w1th,  g_W1th);
    cudaGetSymbolAddress((void**)&w2th,  g_W2th);
    cudaGetSymbolAddress((void**)&biasqk, g_biasqk);
    cudaGetSymbolAddress((void**)&xhf,   g_xhf);
    cudaGetSymbolAddress((void**)&xlf,   g_xlf);
    cudaGetSymbolAddress((void**)&ah,    g_Ah);
    cudaGetSymbolAddress((void**)&part,  g_part);
    cudaGetSymbolAddress((void**)&vh,    g_Vh);
    cudaGetSymbolAddress((void**)&vth,   g_Vth);
    cudaGetSymbolAddress((void**)&op,    g_O);
    cudaGetSymbolAddress((void**)&och,   g_Och);
    cudaGetSymbolAddress((void**)&ocl,   g_Ocl);
    cudaGetSymbolAddress((void**)&h1pre, g_h1pre);
    cudaGetSymbolAddress((void**)&h1,    g_h1);
    cudaGetSymbolAddress((void**)&h1h,   g_h1h);
    cudaGetSymbolAddress((void**)&h1l,   g_h1l);
    cudaGetSymbolAddress((void**)&ffhh,  g_ffhh);
    cudaGetSymbolAddress((void**)&r2pre, g_r2pre);

    lam_kernel<<<1, 64>>>(lq1, lk1, lq2, lk2);
    concat_bias2<<<8, 256>>>(bQ1, bK1, biasqk);
    convW_all<<<14336, dim3(32, 8)>>>(WQ1, WK1, WV, WO, W1, W2,
                                      bqh, wvh, woth, w1th, w2th);
    conv_hilo_f16<<<4096, 256>>>(x, xhf, xlf, 1048576);

    // QK projection (fp16 2-term): emits hi+lo
    gemm_mma<2, 3, 0><<<dim3(16, 32, 1), 256, SM2>>>(
        xhf, xlf, bqh, biasqk, nullptr, nullptr, qkh, qkl, nullptr, nullptr,
        1024, 1024, 1024, 2048, 1.0f, 0);

    // V projection (fp16 2-term), hi only
    gemm_mma<2, 3, 0><<<dim3(16, 32, 1), 256, SM2>>>(
        xhf, xlf, wvh, bV, nullptr, nullptr, vh, nullptr, nullptr, nullptr,
        1024, 1024, 1024, 2048, 1.0f, 0);

    // scores + fused exp (fp16 2-term): writes unnormalized e (fp16) + row partials
    gemm_mma<2, 3, 1><<<dim3(8, 8, 64), 256, SM2>>>(
        qkh, qkl, qkh + 1024, nullptr, nullptr, nullptr, ah, nullptr, part, mask,
        64, 2048, 2048, 1024, 0.03125f, 0);

    // A output (fp32, normalized): only when the harness expects (r2, A)
    if (out_size >= FULL_ELEMS)
        anorm_kernel<<<65536, 256>>>(ah, part, out + R2_ELEMS);

    convVt_f16<<<dim3(32, 4, 64), dim3(32, 8)>>>(vh, vth);

    // AV (fp16 1-term) on unnormalized e; normalization folded into headLN
    gemm_mma<1, 4, 2><<<dim3(1, 8, 64), 256, SM1>>>(
        ah, nullptr, vth, nullptr, nullptr, op, nullptr, nullptr, nullptr, nullptr,
        1024, 1024, 1024, 128, 1.0f, 0);

    headln_kernel<<<8192, 256>>>(op, part, lnhw, lnhb, och, ocl);

    // output projection (fp16 2-term) + residual(x), LN1
    gemm_mma<2, 3, 0><<<dim3(8, 32, 1), 256, SM2>>>(
        och, ocl, woth, bO, x, h1pre, nullptr, nullptr, nullptr, nullptr,
        2048, 2048, 2048, 1024, 1.0f, 0);
    ln1024<<<4096, 256>>>(h1pre, ln1w, ln1b, h1, h1h, h1l);

    // FFN1 (fp16 1-term — isolated experiment), FFN2 (fp16 2-term)
    gemm_mma<1, 3, 0><<<dim3(32, 32, 1), 256, SM1b>>>(
        h1h, nullptr, w1th, b1, nullptr, nullptr, ffhh, nullptr, nullptr, nullptr,
        1024, 1024, 1024, 4096, 1.0f, 1);
    gemm_mma<1, 3, 0><<<dim3(8, 32, 1), 256, SM1b>>>(
        ffhh, nullptr, w2th, b2, h1, r2pre, nullptr, nullptr, nullptr, nullptr,
        4096, 4096, 4096, 1024, 1.0f, 0);
    ln1024<<<4096, 256>>>(r2pre, ln2w, ln2b, out, nullptr, nullptr);
}

// round 15
// speedup vs baseline: 1.7984x; 1.2573x over previous
#include <cuda_runtime.h>
#include <cuda_fp16.h>
#include <math.h>
#include <stddef.h>
#include <stdint.h>

#define B_SZ   4
#define S_SZ   1024
#define D_M    1024
#define H_N    16
#define D_INT  64
#define D_V    128
#define HID    4096
#define NTOK   4096
#define HB     64
#define LAMBDA_INIT 0.3555090675909693f
#define HEADLN_SCALE 0.6444909324090307f
#define R2_ELEMS 4194304
#define FULL_ELEMS 71303168

// ======================= helpers =======================
__device__ __forceinline__ uint32_t smem_u32(const void* p) {
    uint32_t a;
    asm("{ .reg .u64 t; cvta.to.shared.u64 t, %1; cvt.u32.u64 %0, t; }" : "=r"(a) : "l"(p));
    return a;
}
#define CP_ASYNC16(sdst, gsrc) \
    asm volatile("cp.async.cg.shared.global [%0], [%1], 16;" :: "r"(sdst), "l"(gsrc) : "memory")
#define CP_COMMIT() asm volatile("cp.async.commit_group;" ::: "memory")
template<int N> __device__ __forceinline__ void cp_waitg() {
    asm volatile("cp.async.wait_group %0;" :: "n"(N) : "memory");
}

__device__ __forceinline__ void mma_f16(float* d, uint32_t a0, uint32_t a1, uint32_t a2,
                                        uint32_t a3, uint32_t b0, uint32_t b1) {
    asm volatile(
        "mma.sync.aligned.m16n8k16.row.col.f32.f16.f16.f32 "
        "{%0,%1,%2,%3}, {%4,%5,%6,%7}, {%8,%9}, {%0,%1,%2,%3};"
        : "+f"(d[0]), "+f"(d[1]), "+f"(d[2]), "+f"(d[3])
        : "r"(a0), "r"(a1), "r"(a2), "r"(a3), "r"(b0), "r"(b1));
}
__device__ __forceinline__ void ldmx4(uint32_t* r, uint32_t addr) {
    asm volatile("ldmatrix.sync.aligned.m8n8.x4.shared.b16 {%0,%1,%2,%3}, [%4];"
        : "=r"(r[0]), "=r"(r[1]), "=r"(r[2]), "=r"(r[3]) : "r"(addr));
}
__device__ __forceinline__ uint32_t packh2(float a, float b) {
    __half2 p; p.x = __float2half(a); p.y = __float2half(b);
    return *reinterpret_cast<uint32_t*>(&p);
}

// ======================= static scratch =======================
__device__ __align__(16) __half  g_QKVh [(size_t)NTOK * 4096];   // Q|K|V fp16 hi
__device__ __align__(16) __half  g_Bw   [(size_t)4096 * 1024];   // WQ|WK|WV K-major fp16
__device__ __align__(16) __half  g_WOth [(size_t)1024 * 2048];
__device__ __align__(16) __half  g_W1th [(size_t)4096 * 1024];
__device__ __align__(16) __half  g_W2th [(size_t)1024 * 4096];
__device__ __align__(16) float   g_biasqkv[4096];
__device__ __align__(16) __half  g_xhf  [(size_t)NTOK * 1024];
__device__ __align__(16) __half  g_Ah   [(size_t)HB * S_SZ * S_SZ];  // unnormalized exp, fp16
__device__ __align__(16) float   g_part [(size_t)HB * 8 * 8 * 128];  // per-CTA row partial sums
__device__ __align__(16) __half  g_Vth  [(size_t)HB * 128 * 1024];
__device__ __align__(16) __half  g_O    [(size_t)HB * S_SZ * D_V];   // unnormalized O, fp16
__device__ __align__(16) __half  g_Och  [(size_t)NTOK * 2048];
__device__ __align__(16) float   g_h1pre[(size_t)NTOK * D_M];
__device__ __align__(16) float   g_h1   [(size_t)NTOK * D_M];
__device__ __align__(16) __half  g_h1h  [(size_t)NTOK * D_M];
__device__ __align__(16) __half  g_ffhh [(size_t)NTOK * HID];
__device__ __align__(16) float   g_r2pre[(size_t)NTOK * D_M];
__device__ float g_lamscale;

// ======================= lambda =======================
__global__ void lam_kernel(const float* __restrict__ lq1, const float* __restrict__ lk1,
                           const float* __restrict__ lq2, const float* __restrict__ lk2)
{
    __shared__ float s1[64], s2[64];
    int t = threadIdx.x;
    s1[t] = lq1[t] * lk1[t];
    s2[t] = lq2[t] * lk2[t];
    __syncthreads();
    if (t == 0) {
        float d1 = 0.f, d2 = 0.f;
        for (int i = 0; i < 64; i++) { d1 += s1[i]; d2 += s2[i]; }
        g_lamscale = 1.0f - (expf(d1) - expf(d2) + LAMBDA_INIT);
    }
}

// ======================= conversions =======================
// x -> fp16 hi only
__global__ void __launch_bounds__(256) conv_h_f16(
    const float* __restrict__ in, __half* __restrict__ oh, int n4)
{
    int i = blockIdx.x * 256 + threadIdx.x;
    if (i >= n4) return;
    float4 v = reinterpret_cast<const float4*>(in)[i];
    reinterpret_cast<uint32_t*>(oh)[i * 2]     = packh2(v.x, v.y);
    reinterpret_cast<uint32_t*>(oh)[i * 2 + 1] = packh2(v.z, v.w);
}

// fused weight transpose-convert (all six weights in one launch)
__global__ void convW_all(
    const float* __restrict__ WQ1, const float* __restrict__ WK1, const float* __restrict__ WV,
    const float* __restrict__ WO,  const float* __restrict__ W1,  const float* __restrict__ W2,
    __half* __restrict__ bw, __half* __restrict__ woth,
    __half* __restrict__ w1th, __half* __restrict__ w2th)
{
    __shared__ float t[32][33];
    int lb = blockIdx.x;
    const float* in; __half* oh; int K, dout, gxm;
    if      (lb < 1024)  { in = WQ1; oh = bw;                  K = 1024; dout = 64;   gxm = 32;  }
    else if (lb < 2048)  { in = WK1; oh = bw + 1024 * 1024;    K = 1024; dout = 64;   gxm = 32;  lb -= 1024; }
    else if (lb < 4096)  { in = WV;  oh = bw + 2048 * 1024;    K = 1024; dout = 128;  gxm = 32;  lb -= 2048; }
    else if (lb < 6144)  { in = WO;  oh = woth;                K = 2048; dout = 1024; gxm = 64;  lb -= 4096; }
    else if (lb < 10240) { in = W1;  oh = w1th;                K = 1024; dout = 4096; gxm = 32;  lb -= 6144; }
    else                 { in = W2;  oh = w2th;                K = 4096; dout = 1024; gxm = 128; lb -= 10240; }
    int gx = lb % gxm, gy = lb / gxm;
    int k0 = gx * 32, n0 = gy * 32;
    int h = n0 / dout, d0 = n0 - h * dout;
    const float* src = in + (size_t)h * K * dout + d0;
    for (int r = threadIdx.y; r < 32; r += 8)
        t[r][threadIdx.x] = src[(size_t)(k0 + r) * dout + threadIdx.x];
    __syncthreads();
    for (int r = threadIdx.y; r < 32; r += 8)
        oh[(size_t)(n0 + r) * K + k0 + threadIdx.x] = __float2half(t[threadIdx.x][r]);
}

// V transpose (fp16 hi): Vt[z][v][t] from QKVh[(b*1024+t)*4096 + 2048 + h*128 + v]
__global__ void convVt_f16(const __half* __restrict__ sh, __half* __restrict__ oh)
{
    __shared__ __half th[32][33];
    int z = blockIdx.z, h = z >> 2, b = z & 3;
    int t0 = blockIdx.x * 32, v0 = blockIdx.y * 32;
    for (int r = threadIdx.y; r < 32; r += 8)
        th[r][threadIdx.x] = sh[(size_t)(b * 1024 + t0 + r) * 4096 + 2048 + h * 128 + v0 + threadIdx.x];
    __syncthreads();
    size_t base = (size_t)z * 131072;
    for (int r = threadIdx.y; r < 32; r += 8)
        oh[base + (size_t)(v0 + r) * 1024 + t0 + threadIdx.x] = th[threadIdx.x][r];
}

__global__ void concat_bias3(const float* __restrict__ bq, const float* __restrict__ bk,
                             const float* __restrict__ bv, float* __restrict__ o)
{
    int t = blockIdx.x * 256 + threadIdx.x;
    if (t < 1024) o[t] = bq[t];
    else if (t < 2048) o[t] = bk[t - 1024];
    else if (t < 4096) o[t] = bv[t - 2048];
}

// ======================= tensor-core GEMM (fp16 mma.sync) ====================
// MODE 0: plain GEMM. MODE 1: scores, fused exp epilogue. MODE 2: AV batched.
template<int TERMS, int NS, int MODE>
__global__ void __launch_bounds__(256, 2) gemm_mma(
    const __half* __restrict__ Ah, const __half* __restrict__ Al,
    const __half* __restrict__ Bh,
    const float* __restrict__ bias, const float* __restrict__ res,
    float* __restrict__ cout, __half* __restrict__ outh,
    float* __restrict__ partial, const int* __restrict__ mask,
    int K, int lda, int ldb, int ldc, float alpha, int relu)
{
    constexpr int NTILE = TERMS + 1;
    constexpr int STG = NTILE * 10240;
    constexpr uint32_t oAl = 10240;
    constexpr uint32_t oBh = (TERMS >= 2) ? 20480u : 10240u;
    extern __shared__ char dsm[];
    const int tid = threadIdx.x;
    const int lane = tid & 31, wid = tid >> 5;
    const int wy = wid >> 2, wx = wid & 3;       // warp tile: 64(M) x 32(N)
    const int m0 = blockIdx.y * 128, n0 = blockIdx.x * 128;
    const uint32_t smbase = smem_u32(dsm);

    size_t aoff = 0, boff = 0, coff = 0;
    if (MODE == 1) {
        int z = blockIdx.z, h = z >> 2, b = z & 3;
        aoff = (size_t)(b << 10) * lda + (h << 6);
        boff = (size_t)(b << 10) * ldb + (h << 6);
        coff = (size_t)z << 20;
    } else if (MODE == 2) {
        int z = blockIdx.z;
        aoff = (size_t)z << 20;
        boff = (size_t)z << 17;
        coff = (size_t)z << 17;
    }

    float acc[4][4][4];
#pragma unroll
    for (int i = 0; i < 4; i++)
#pragma unroll
        for (int j = 0; j < 4; j++)
#pragma unroll
            for (int q = 0; q < 4; q++) acc[i][j][q] = 0.f;

    const int niter = K >> 5;

    auto issue_tile = [&](int it, int slot) {
        int k0 = it << 5;
        uint32_t sb = smbase + slot * STG;
#pragma unroll
        for (int i = 0; i < 2; i++) {
            int l = tid + (i << 8);
            int row = l >> 2, c16 = l & 3;
            size_t aidx = aoff + (size_t)(m0 + row) * lda + k0 + (c16 << 3);
            size_t bidx = boff + (size_t)(n0 + row) * ldb + k0 + (c16 << 3);
            uint32_t so = (uint32_t)(row * 80 + (c16 << 4));
            CP_ASYNC16(sb + so,       Ah + aidx);
            if (TERMS >= 2) CP_ASYNC16(sb + oAl + so, Al + aidx);
            CP_ASYNC16(sb + oBh + so, Bh + bidx);
        }
        CP_COMMIT();
    };

#pragma unroll
    for (int s = 0; s < NS - 1; s++)
        if (s < niter) issue_tile(s, s);

    const int a_row = (wy << 6) + (lane & 7) + ((lane >> 3) & 1) * 8;
    const int a_kb  = (lane >> 4) << 4;
    const int b_row8 = (wx << 5) + (lane & 7);
    const int b_k4   = ((lane >> 3) & 3) << 4;

    int cs = 0, is_ = NS - 1;
#pragma unroll 1
    for (int it = 0; it < niter; it++) {
        if (it + NS - 1 < niter) {
            issue_tile(it + NS - 1, is_);
            cp_waitg<NS - 1>();
        } else {
            cp_waitg<0>();
        }
        __syncthreads();

        uint32_t base = smbase + cs * STG;
        uint32_t pAh = base;
        uint32_t pAl = base + oAl;
        uint32_t pBh = base + oBh;

        uint32_t b4[4][4];
#pragma unroll
        for (int nt = 0; nt < 4; nt++) {
            uint32_t bo = (uint32_t)((b_row8 + (nt << 3)) * 80 + b_k4);
            ldmx4(b4[nt], pBh + bo);
        }

#pragma unroll
        for (int ks = 0; ks < 2; ks++) {
            const int ksb = ks << 5;
#pragma unroll
            for (int mt = 0; mt < 4; mt++) {
                uint32_t ao = (uint32_t)((a_row + (mt << 4)) * 80 + ksb + a_kb);
                uint32_t ahf[4], alf[4];
                ldmx4(ahf, pAh + ao);
                if (TERMS >= 2) ldmx4(alf, pAl + ao);
#pragma unroll
                for (int nt = 0; nt < 4; nt++) {
                    mma_f16(acc[mt][nt], ahf[0], ahf[1], ahf[2], ahf[3],
                            b4[nt][ks * 2], b4[nt][ks * 2 + 1]);
                    if (TERMS >= 2)
                        mma_f16(acc[mt][nt], alf[0], alf[1], alf[2], alf[3],
                                b4[nt][ks * 2], b4[nt][ks * 2 + 1]);
                }
            }
        }
        __syncthreads();
        cs = (cs + 1 == NS) ? 0 : cs + 1;
        is_ = (is_ + 1 == NS) ? 0 : is_ + 1;
    }

    if (MODE == 1) {
        // fused exp + row-partial-sum epilogue (scores; |s|<1 so exp is safe)
        const int b = blockIdx.z & 3;
        const int* mrow = mask + (b << 10) + n0;
        float rowacc[4][2];
#pragma unroll
        for (int mt = 0; mt < 4; mt++) { rowacc[mt][0] = 0.f; rowacc[mt][1] = 0.f; }
#pragma unroll
        for (int mt = 0; mt < 4; mt++) {
#pragma unroll
            for (int hf = 0; hf < 2; hf++) {
                int row = m0 + (mt << 4) + (wy << 6) + (lane >> 2) + (hf << 3);
                float rsum = 0.f;
#pragma unroll
                for (int nt = 0; nt < 4; nt++) {
                    int cl = (wx << 5) + (nt << 3) + ((lane & 3) << 1);
                    float e0 = mrow[cl]     ? __expf(acc[mt][nt][hf * 2]     * alpha) : 0.f;
                    float e1 = mrow[cl + 1] ? __expf(acc[mt][nt][hf * 2 + 1] * alpha) : 0.f;
                    rsum += e0 + e1;
                    *reinterpret_cast<uint32_t*>(outh + coff + (size_t)row * 1024 + n0 + cl)
                        = packh2(e0, e1);
                }
                rowacc[mt][hf] += rsum;
            }
        }
        float (*rs)[4] = reinterpret_cast<float(*)[4]>(dsm);
#pragma unroll
        for (int mt = 0; mt < 4; mt++)
#pragma unroll
            for (int hf = 0; hf < 2; hf++) {
                float v = rowacc[mt][hf];
                v += __shfl_xor_sync(0xffffffffu, v, 1);
                v += __shfl_xor_sync(0xffffffffu, v, 2);
                if ((lane & 3) == 0) {
                    int rl = (wy << 6) + (mt << 4) + (lane >> 2) + (hf << 3);
                    rs[rl][wx] = v;
                }
            }
        __syncthreads();
        if (tid < 128) {
            float s4 = rs[tid][0] + rs[tid][1] + rs[tid][2] + rs[tid][3];
            partial[(((size_t)blockIdx.z << 6) + (blockIdx.y << 3) + blockIdx.x) * 128 + tid] = s4;
        }
        return;
    }

    // generic epilogue
#pragma unroll
    for (int mt = 0; mt < 4; mt++) {
#pragma unroll
        for (int nt = 0; nt < 4; nt++) {
#pragma unroll
            for (int hf = 0; hf < 2; hf++) {
                int row = m0 + (wy << 6) + (mt << 4) + (lane >> 2) + (hf << 3);
                int col = n0 + (wx << 5) + (nt << 3) + ((lane & 3) << 1);
                float v0 = acc[mt][nt][hf * 2]     * alpha;
                float v1 = acc[mt][nt][hf * 2 + 1] * alpha;
                if (bias) { v0 += bias[col]; v1 += bias[col + 1]; }
                if (res) {
                    float2 rv = *reinterpret_cast<const float2*>(res + (size_t)row * ldc + col);
                    v0 += rv.x; v1 += rv.y;
                }
                if (relu) { v0 = fmaxf(v0, 0.f); v1 = fmaxf(v1, 0.f); }
                size_t oidx = coff + (size_t)row * ldc + col;
                if (cout) *reinterpret_cast<float2*>(cout + oidx) = make_float2(v0, v1);
                if (outh) *reinterpret_cast<uint32_t*>(outh + oidx) = packh2(v0, v1);
            }
        }
    }
}

// ======================= A normalization: A = e * lamscale/rowsum (fp32) ====
__global__ void __launch_bounds__(256) anorm_kernel(
    const __half* __restrict__ e, const float* __restrict__ partial, float* __restrict__ A)
{
    size_t row = blockIdx.x;
    int z = (int)(row >> 10), s = (int)(row & 1023);
    size_t base = (((size_t)(z << 6) + ((s >> 7) << 3)) << 7) + (s & 127);
    float sum = 0.f;
#pragma unroll
    for (int nb = 0; nb < 8; nb++) sum += partial[base + (nb << 7)];
    float sc = g_lamscale / sum;
    int t = threadIdx.x;
#pragma unroll
    for (int i = 0; i < 2; i++) {
        int c = (t + (i << 8)) << 1;
        __half2 p = *reinterpret_cast<const __half2*>(e + row * 1024 + c);
        float2 o = make_float2(__half2float(p.x) * sc, __half2float(p.y) * sc);
        *reinterpret_cast<float2*>(A + row * 1024 + c) = o;
    }
}

// ======================= per-head LN(128) + concat (normalizes fp16 O) ======
__global__ void __launch_bounds__(256) headln_kernel(
    const __half* __restrict__ O, const float* __restrict__ partial,
    const float* __restrict__ w, const float* __restrict__ bvec,
    __half* __restrict__ och)
{
    int gw = blockIdx.x * 8 + (threadIdx.x >> 5);
    int lane = threadIdx.x & 31;
    int z = gw >> 10, s_ = gw & 1023;
    size_t pbase = (((size_t)(z << 6) + ((s_ >> 7) << 3)) << 7) + (s_ & 127);
    float sum = 0.f;
#pragma unroll
    for (int nb = 0; nb < 8; nb++) sum += partial[pbase + (nb << 7)];
    float sc = g_lamscale / sum;

    const __half* xr = O + (size_t)gw * 128;
    float x0 = __half2float(xr[lane])      * sc, x1 = __half2float(xr[lane + 32]) * sc,
          x2 = __half2float(xr[lane + 64]) * sc, x3 = __half2float(xr[lane + 96]) * sc;
    float s = x0 + x1 + x2 + x3;
#pragma unroll
    for (int o = 16; o; o >>= 1) s += __shfl_xor_sync(0xffffffffu, s, o);
    float mean = s * (1.f / 128.f);
    float d0 = x0 - mean, d1 = x1 - mean, d2 = x2 - mean, d3 = x3 - mean;
    float q = d0 * d0 + d1 * d1 + d2 * d2 + d3 * d3;
#pragma unroll
    for (int o = 16; o; o >>= 1) q += __shfl_xor_sync(0xffffffffu, q, o);
    float rstd = rsqrtf(q * (1.f / 128.f) + 1e-5f);

    int h = z >> 2, b = z & 3;
    size_t base = ((size_t)(b * S_SZ + s_)) * 2048 + h * 128;
    och[base + lane]      = __float2half((d0 * rstd * w[lane]      + bvec[lane])      * HEADLN_SCALE);
    och[base + lane + 32] = __float2half((d1 * rstd * w[lane + 32] + bvec[lane + 32]) * HEADLN_SCALE);
    och[base + lane + 64] = __float2half((d2 * rstd * w[lane + 64] + bvec[lane + 64]) * HEADLN_SCALE);
    och[base + lane + 96] = __float2half((d3 * rstd * w[lane + 96] + bvec[lane + 96]) * HEADLN_SCALE);
}

// ======================= LayerNorm 1024 (optional fp16 hi out) ==============
__global__ void __launch_bounds__(256) ln1024(
    const float* __restrict__ X, const float* __restrict__ w,
    const float* __restrict__ bvec, float* __restrict__ out,
    __half* __restrict__ outh)
{
    __shared__ float red[8];
    __shared__ float bc;
    size_t row = blockIdx.x;
    const float* xr = X + row * 1024;
    int t = threadIdx.x;
    int wid = t >> 5, lane = t & 31;

    float v[4];
    float s = 0.f;
#pragma unroll
    for (int i = 0; i < 4; i++) { v[i] = xr[t + i * 256]; s += v[i]; }
#pragma unroll
    for (int o = 16; o; o >>= 1) s += __shfl_xor_sync(0xffffffffu, s, o);
    if (lane == 0) red[wid] = s;
    __syncthreads();
    if (t < 32) {
        float s2 = (t < 8) ? red[t] : 0.f;
#pragma unroll
        for (int o = 4; o; o >>= 1) s2 += __shfl_xor_sync(0xffffffffu, s2, o);
        if (t == 0) bc = s2 * (1.f / 1024.f);
    }
    __syncthreads();
    float mean = bc;

    float q = 0.f;
#pragma unroll
    for (int i = 0; i < 4; i++) { float d = v[i] - mean; q += d * d; }
#pragma unroll
    for (int o = 16; o; o >>= 1) q += __shfl_xor_sync(0xffffffffu, q, o);
    __syncthreads();
    if (lane == 0) red[wid] = q;
    __syncthreads();
    if (t < 32) {
        float q2 = (t < 8) ? red[t] : 0.f;
#pragma unroll
        for (int o = 4; o; o >>= 1) q2 += __shfl_xor_sync(0xffffffffu, q2, o);
        if (t == 0) bc = rsqrtf(q2 * (1.f / 1024.f) + 1e-5f);
    }
    __syncthreads();
    float rstd = bc;
#pragma unroll
    for (int i = 0; i < 4; i++) {
        int c = t + i * 256;
        float vv = (v[i] - mean) * rstd * w[c] + bvec[c];
        out[row * 1024 + c] = vv;
        if (outh) outh[row * 1024 + c] = __float2half(vv);
    }
}

// ======================= host launcher ======================================
extern "C" void kernel_launch(void* const* d_in, const int* in_sizes, int n_in,
                              void* d_out, int out_size)
{
    const float* x    = (const float*)d_in[0];
    const int*   mask = (const int*)  d_in[1];
    const float* WQ1  = (const float*)d_in[2];
    const float* bQ1  = (const float*)d_in[3];
    const float* WK1  = (const float*)d_in[4];
    const float* bK1  = (const float*)d_in[5];
    const float* WV   = (const float*)d_in[6];
    const float* bV   = (const float*)d_in[7];
    const float* lnhw = (const float*)d_in[8];
    const float* lnhb = (const float*)d_in[9];
    const float* WO   = (const float*)d_in[10];
    const float* bO   = (const float*)d_in[11];
    const float* ln1w = (const float*)d_in[12];
    const float* ln1b = (const float*)d_in[13];
    const float* ln2w = (const float*)d_in[14];
    const float* ln2b = (const float*)d_in[15];
    const float* W1   = (const float*)d_in[16];
    const float* b1   = (const float*)d_in[17];
    const float* W2   = (const float*)d_in[18];
    const float* b2   = (const float*)d_in[19];
    const float* lq1  = (const float*)d_in[20];
    const float* lk1  = (const float*)d_in[21];
    const float* lq2  = (const float*)d_in[22];
    const float* lk2  = (const float*)d_in[23];

    float* out = (float*)d_out;

    const int SM1 = 3 * 2 * 10240;   // 61440: 1-term, 3-stage
    const int SM1c = 4 * 2 * 10240;  // 81920: 1-term, 4-stage (AV)
    cudaFuncSetAttribute(gemm_mma<1, 3, 0>, cudaFuncAttributeMaxDynamicSharedMemorySize, SM1);
    cudaFuncSetAttribute(gemm_mma<1, 3, 1>, cudaFuncAttributeMaxDynamicSharedMemorySize, SM1);
    cudaFuncSetAttribute(gemm_mma<1, 4, 2>, cudaFuncAttributeMaxDynamicSharedMemorySize, SM1c);

    float *h1pre, *h1, *r2pre, *biasqkv, *part;
    __half *qkvh, *bw, *woth, *w1th, *w2th;
    __half *xhf, *ah, *vth, *oph, *och, *h1h, *ffhh;
    cudaGetSymbolAddress((void**)&qkvh,  g_QKVh);
    cudaGetSymbolAddress((void**)&bw,    g_Bw);
    cudaGetSymbolAddress((void**)&woth,  g_WOth);
    cudaGetSymbolAddress((void**)&w1th,  g_W1th);
    cudaGetSymbolAddress((void**)&w2th,  g_W2th);
    cudaGetSymbolAddress((void**)&biasqkv, g_biasqkv);
    cudaGetSymbolAddress((void**)&xhf,   g_xhf);
    cudaGetSymbolAddress((void**)&ah,    g_Ah);
    cudaGetSymbolAddress((void**)&part,  g_part);
    cudaGetSymbolAddress((void**)&vth,   g_Vth);
    cudaGetSymbolAddress((void**)&oph,   g_O);
    cudaGetSymbolAddress((void**)&och,   g_Och);
    cudaGetSymbolAddress((void**)&h1pre, g_h1pre);
    cudaGetSymbolAddress((void**)&h1,    g_h1);
    cudaGetSymbolAddress((void**)&h1h,   g_h1h);
    cudaGetSymbolAddress((void**)&ffhh,  g_ffhh);
    cudaGetSymbolAddress((void**)&r2pre, g_r2pre);

    lam_kernel<<<1, 64>>>(lq1, lk1, lq2, lk2);
    concat_bias3<<<16, 256>>>(bQ1, bK1, bV, biasqkv);
    convW_all<<<14336, dim3(32, 8)>>>(WQ1, WK1, WV, WO, W1, W2, bw, woth, w1th, w2th);
    conv_h_f16<<<4096, 256>>>(x, xhf, 1048576);

    // fused QKV projection (fp16 1-term): [4096, 4096], K=1024
    gemm_mma<1, 3, 0><<<dim3(32, 32, 1), 256, SM1>>>(
        xhf, nullptr, bw, biasqkv, nullptr, nullptr, qkvh, nullptr, nullptr,
        1024, 1024, 1024, 4096, 1.0f, 0);

    // scores + fused exp (fp16 1-term): unnormalized e (fp16) + row partials
    gemm_mma<1, 3, 1><<<dim3(8, 8, 64), 256, SM1>>>(
        qkvh, nullptr, qkvh + 1024, nullptr, nullptr, nullptr, ah, part, mask,
        64, 4096, 4096, 1024, 0.03125f, 0);

    // A output (fp32, normalized)
    if (out_size >= FULL_ELEMS)
        anorm_kernel<<<65536, 256>>>(ah, part, out + R2_ELEMS);

    convVt_f16<<<dim3(32, 4, 64), dim3(32, 8)>>>(qkvh, vth);

    // AV (fp16 1-term) on unnormalized e -> fp16 O; normalization folded into headLN
    gemm_mma<1, 4, 2><<<dim3(1, 8, 64), 256, SM1c>>>(
        ah, nullptr, vth, nullptr, nullptr, nullptr, oph, nullptr, nullptr,
        1024, 1024, 1024, 128, 1.0f, 0);

    headln_kernel<<<8192, 256>>>(oph, part, lnhw, lnhb, och);

    // output projection (fp16 1-term) + residual(x), LN1
    gemm_mma<1, 3, 0><<<dim3(8, 32, 1), 256, SM1>>>(
        och, nullptr, woth, bO, x, h1pre, nullptr, nullptr, nullptr,
        2048, 2048, 2048, 1024, 1.0f, 0);
    ln1024<<<4096, 256>>>(h1pre, ln1w, ln1b, h1, h1h);

    // FFN (fp16 1-term): relu(h1 @ W1 + b1) @ W2 + b2 + h1, LN2 -> out
    gemm_mma<1, 3, 0><<<dim3(32, 32, 1), 256, SM1>>>(
        h1h, nullptr, w1th, b1, nullptr, nullptr, ffhh, nullptr, nullptr,
        1024, 1024, 1024, 4096, 1.0f, 1);
    gemm_mma<1, 3, 0><<<dim3(8, 32, 1), 256, SM1>>>(
        ffhh, nullptr, w2th, b2, h1, r2pre, nullptr, nullptr, nullptr,
        4096, 4096, 4096, 1024, 1.0f, 0);
    ln1024<<<4096, 256>>>(r2pre, ln2w, ln2b, out, nullptr);
}

// round 16
// speedup vs baseline: 1.9278x; 1.0720x over previous
#include <cuda_runtime.h>
#include <cuda_fp16.h>
#include <math.h>
#include <stddef.h>
#include <stdint.h>

#define B_SZ   4
#define S_SZ   1024
#define D_M    1024
#define H_N    16
#define D_INT  64
#define D_V    128
#define HID    4096
#define NTOK   4096
#define HB     64
#define LAMBDA_INIT 0.3555090675909693f
#define HEADLN_SCALE 0.6444909324090307f
#define R2_ELEMS 4194304
#define FULL_ELEMS 71303168

// ======================= helpers =======================
__device__ __forceinline__ uint32_t smem_u32(const void* p) {
    uint32_t a;
    asm("{ .reg .u64 t; cvta.to.shared.u64 t, %1; cvt.u32.u64 %0, t; }" : "=r"(a) : "l"(p));
    return a;
}
#define CP_ASYNC16(sdst, gsrc) \
    asm volatile("cp.async.cg.shared.global [%0], [%1], 16;" :: "r"(sdst), "l"(gsrc) : "memory")
#define CP_COMMIT() asm volatile("cp.async.commit_group;" ::: "memory")
template<int N> __device__ __forceinline__ void cp_waitg() {
    asm volatile("cp.async.wait_group %0;" :: "n"(N) : "memory");
}

__device__ __forceinline__ void mma_f16(float* d, uint32_t a0, uint32_t a1, uint32_t a2,
                                        uint32_t a3, uint32_t b0, uint32_t b1) {
    asm volatile(
        "mma.sync.aligned.m16n8k16.row.col.f32.f16.f16.f32 "
        "{%0,%1,%2,%3}, {%4,%5,%6,%7}, {%8,%9}, {%0,%1,%2,%3};"
        : "+f"(d[0]), "+f"(d[1]), "+f"(d[2]), "+f"(d[3])
        : "r"(a0), "r"(a1), "r"(a2), "r"(a3), "r"(b0), "r"(b1));
}
__device__ __forceinline__ void ldmx4(uint32_t* r, uint32_t addr) {
    asm volatile("ldmatrix.sync.aligned.m8n8.x4.shared.b16 {%0,%1,%2,%3}, [%4];"
        : "=r"(r[0]), "=r"(r[1]), "=r"(r[2]), "=r"(r[3]) : "r"(addr));
}
__device__ __forceinline__ uint32_t packh2(float a, float b) {
    __half2 p; p.x = __float2half(a); p.y = __float2half(b);
    return *reinterpret_cast<uint32_t*>(&p);
}

// BK=64 tile geometry: 128 rows x 144 bytes (128 data + 16 pad)
#define ROWB 144
#define TILEB 18432

// ======================= static scratch =======================
__device__ __align__(16) __half  g_QKVh [(size_t)NTOK * 4096];   // Q|K|V fp16 hi
__device__ __align__(16) __half  g_Bw   [(size_t)4096 * 1024];   // WQ|WK|WV K-major fp16
__device__ __align__(16) __half  g_WOth [(size_t)1024 * 2048];
__device__ __align__(16) __half  g_W1th [(size_t)4096 * 1024];
__device__ __align__(16) __half  g_W2th [(size_t)1024 * 4096];
__device__ __align__(16) float   g_biasqkv[4096];
__device__ __align__(16) __half  g_xhf  [(size_t)NTOK * 1024];
__device__ __align__(16) __half  g_Ah   [(size_t)HB * S_SZ * S_SZ];  // unnormalized exp, fp16
__device__ __align__(16) float   g_part [(size_t)HB * 8 * 8 * 128];  // per-CTA row partial sums
__device__ __align__(16) __half  g_Vth  [(size_t)HB * 128 * 1024];
__device__ __align__(16) __half  g_O    [(size_t)HB * S_SZ * D_V];   // unnormalized O, fp16
__device__ __align__(16) __half  g_Och  [(size_t)NTOK * 2048];
__device__ __align__(16) float   g_h1pre[(size_t)NTOK * D_M];
__device__ __align__(16) float   g_h1   [(size_t)NTOK * D_M];
__device__ __align__(16) __half  g_h1h  [(size_t)NTOK * D_M];
__device__ __align__(16) __half  g_ffhh [(size_t)NTOK * HID];
__device__ __align__(16) float   g_r2pre[(size_t)NTOK * D_M];
__device__ float g_lamscale;

// ======================= lambda =======================
__global__ void lam_kernel(const float* __restrict__ lq1, const float* __restrict__ lk1,
                           const float* __restrict__ lq2, const float* __restrict__ lk2)
{
    __shared__ float s1[64], s2[64];
    int t = threadIdx.x;
    s1[t] = lq1[t] * lk1[t];
    s2[t] = lq2[t] * lk2[t];
    __syncthreads();
    if (t == 0) {
        float d1 = 0.f, d2 = 0.f;
        for (int i = 0; i < 64; i++) { d1 += s1[i]; d2 += s2[i]; }
        g_lamscale = 1.0f - (expf(d1) - expf(d2) + LAMBDA_INIT);
    }
}

// ======================= conversions =======================
__global__ void __launch_bounds__(256) conv_h_f16(
    const float* __restrict__ in, __half* __restrict__ oh, int n4)
{
    int i = blockIdx.x * 256 + threadIdx.x;
    if (i >= n4) return;
    float4 v = reinterpret_cast<const float4*>(in)[i];
    reinterpret_cast<uint32_t*>(oh)[i * 2]     = packh2(v.x, v.y);
    reinterpret_cast<uint32_t*>(oh)[i * 2 + 1] = packh2(v.z, v.w);
}

__global__ void convW_all(
    const float* __restrict__ WQ1, const float* __restrict__ WK1, const float* __restrict__ WV,
    const float* __restrict__ WO,  const float* __restrict__ W1,  const float* __restrict__ W2,
    __half* __restrict__ bw, __half* __restrict__ woth,
    __half* __restrict__ w1th, __half* __restrict__ w2th)
{
    __shared__ float t[32][33];
    int lb = blockIdx.x;
    const float* in; __half* oh; int K, dout, gxm;
    if      (lb < 1024)  { in = WQ1; oh = bw;                  K = 1024; dout = 64;   gxm = 32;  }
    else if (lb < 2048)  { in = WK1; oh = bw + 1024 * 1024;    K = 1024; dout = 64;   gxm = 32;  lb -= 1024; }
    else if (lb < 4096)  { in = WV;  oh = bw + 2048 * 1024;    K = 1024; dout = 128;  gxm = 32;  lb -= 2048; }
    else if (lb < 6144)  { in = WO;  oh = woth;                K = 2048; dout = 1024; gxm = 64;  lb -= 4096; }
    else if (lb < 10240) { in = W1;  oh = w1th;                K = 1024; dout = 4096; gxm = 32;  lb -= 6144; }
    else                 { in = W2;  oh = w2th;                K = 4096; dout = 1024; gxm = 128; lb -= 10240; }
    int gx = lb % gxm, gy = lb / gxm;
    int k0 = gx * 32, n0 = gy * 32;
    int h = n0 / dout, d0 = n0 - h * dout;
    const float* src = in + (size_t)h * K * dout + d0;
    for (int r = threadIdx.y; r < 32; r += 8)
        t[r][threadIdx.x] = src[(size_t)(k0 + r) * dout + threadIdx.x];
    __syncthreads();
    for (int r = threadIdx.y; r < 32; r += 8)
        oh[(size_t)(n0 + r) * K + k0 + threadIdx.x] = __float2half(t[threadIdx.x][r]);
}

__global__ void convVt_f16(const __half* __restrict__ sh, __half* __restrict__ oh)
{
    __shared__ __half th[32][33];
    int z = blockIdx.z, h = z >> 2, b = z & 3;
    int t0 = blockIdx.x * 32, v0 = blockIdx.y * 32;
    for (int r = threadIdx.y; r < 32; r += 8)
        th[r][threadIdx.x] = sh[(size_t)(b * 1024 + t0 + r) * 4096 + 2048 + h * 128 + v0 + threadIdx.x];
    __syncthreads();
    size_t base = (size_t)z * 131072;
    for (int r = threadIdx.y; r < 32; r += 8)
        oh[base + (size_t)(v0 + r) * 1024 + t0 + threadIdx.x] = th[threadIdx.x][r];
}

__global__ void concat_bias3(const float* __restrict__ bq, const float* __restrict__ bk,
                             const float* __restrict__ bv, float* __restrict__ o)
{
    int t = blockIdx.x * 256 + threadIdx.x;
    if (t < 1024) o[t] = bq[t];
    else if (t < 2048) o[t] = bk[t - 1024];
    else if (t < 4096) o[t] = bv[t - 2048];
}

// ======================= tensor-core GEMM (fp16 mma.sync, BK=64) ============
// MODE 0: plain GEMM. MODE 1: scores, fused exp epilogue. MODE 2: AV batched.
template<int NS, int MODE>
__global__ void __launch_bounds__(256, 2) gemm_mma(
    const __half* __restrict__ Ah, const __half* __restrict__ Bh,
    const float* __restrict__ bias, const float* __restrict__ res,
    float* __restrict__ cout, __half* __restrict__ outh,
    float* __restrict__ partial, const int* __restrict__ mask,
    int K, int lda, int ldb, int ldc, float alpha, int relu)
{
    constexpr int STG = 2 * TILEB;
    extern __shared__ char dsm[];
    const int tid = threadIdx.x;
    const int lane = tid & 31, wid = tid >> 5;
    const int wy = wid >> 2, wx = wid & 3;       // warp tile: 64(M) x 32(N)
    const int m0 = blockIdx.y * 128, n0 = blockIdx.x * 128;
    const uint32_t smbase = smem_u32(dsm);

    size_t aoff = 0, boff = 0, coff = 0;
    if (MODE == 1) {
        int z = blockIdx.z, h = z >> 2, b = z & 3;
        aoff = (size_t)(b << 10) * lda + (h << 6);
        boff = (size_t)(b << 10) * ldb + (h << 6);
        coff = (size_t)z << 20;
    } else if (MODE == 2) {
        int z = blockIdx.z;
        aoff = (size_t)z << 20;
        boff = (size_t)z << 17;
        coff = (size_t)z << 17;
    }

    float acc[4][4][4];
#pragma unroll
    for (int i = 0; i < 4; i++)
#pragma unroll
        for (int j = 0; j < 4; j++)
#pragma unroll
            for (int q = 0; q < 4; q++) acc[i][j][q] = 0.f;

    const int niter = K >> 6;

    auto issue_tile = [&](int it, int slot) {
        int k0 = it << 6;
        uint32_t sb = smbase + slot * STG;
#pragma unroll
        for (int i = 0; i < 4; i++) {
            int l = tid + (i << 8);
            int row = l >> 3, c16 = l & 7;     // 8 x 16B chunks per 128B row
            size_t aidx = aoff + (size_t)(m0 + row) * lda + k0 + (c16 << 3);
            size_t bidx = boff + (size_t)(n0 + row) * ldb + k0 + (c16 << 3);
            uint32_t so = (uint32_t)(row * ROWB + (c16 << 4));
            CP_ASYNC16(sb + so,         Ah + aidx);
            CP_ASYNC16(sb + TILEB + so, Bh + bidx);
        }
        CP_COMMIT();
    };

#pragma unroll
    for (int s = 0; s < NS - 1; s++)
        if (s < niter) issue_tile(s, s);

    const int a_row = (wy << 6) + (lane & 7) + ((lane >> 3) & 1) * 8;  // + mt*16
    const int a_kb  = (lane >> 4) << 4;
    const int b_row8 = (wx << 5) + (lane & 7);                         // + nt*8
    const int b_k4   = ((lane >> 3) & 3) << 4;

    int cs = 0, is_ = NS - 1;
#pragma unroll 1
    for (int it = 0; it < niter; it++) {
        if (it + NS - 1 < niter) {
            issue_tile(it + NS - 1, is_);
            cp_waitg<NS - 1>();
        } else {
            cp_waitg<0>();
        }
        __syncthreads();

        uint32_t pAh = smbase + cs * STG;
        uint32_t pBh = pAh + TILEB;

#pragma unroll
        for (int half = 0; half < 2; half++) {
            const int hb = half << 6;   // 0 or 64 bytes (32 k-elems)
            uint32_t b4[4][4];
#pragma unroll
            for (int nt = 0; nt < 4; nt++) {
                uint32_t bo = (uint32_t)((b_row8 + (nt << 3)) * ROWB + hb + b_k4);
                ldmx4(b4[nt], pBh + bo);
            }
#pragma unroll
            for (int ks = 0; ks < 2; ks++) {
                const int ksb = hb + (ks << 5);
#pragma unroll
                for (int mt = 0; mt < 4; mt++) {
                    uint32_t ao = (uint32_t)((a_row + (mt << 4)) * ROWB + ksb + a_kb);
                    uint32_t ahf[4];
                    ldmx4(ahf, pAh + ao);
#pragma unroll
                    for (int nt = 0; nt < 4; nt++)
                        mma_f16(acc[mt][nt], ahf[0], ahf[1], ahf[2], ahf[3],
                                b4[nt][ks * 2], b4[nt][ks * 2 + 1]);
                }
            }
        }
        __syncthreads();
        cs = (cs + 1 == NS) ? 0 : cs + 1;
        is_ = (is_ + 1 == NS) ? 0 : is_ + 1;
    }

    if (MODE == 1) {
        // fused exp + row-partial-sum epilogue (|s|<1, exp safe)
        const int b = blockIdx.z & 3;
        const int* mrow = mask + (b << 10) + n0;
        float rowacc[4][2];
#pragma unroll
        for (int mt = 0; mt < 4; mt++) { rowacc[mt][0] = 0.f; rowacc[mt][1] = 0.f; }
#pragma unroll
        for (int mt = 0; mt < 4; mt++) {
#pragma unroll
            for (int hf = 0; hf < 2; hf++) {
                int row = m0 + (mt << 4) + (wy << 6) + (lane >> 2) + (hf << 3);
                float rsum = 0.f;
#pragma unroll
                for (int nt = 0; nt < 4; nt++) {
                    int cl = (wx << 5) + (nt << 3) + ((lane & 3) << 1);
                    float e0 = mrow[cl]     ? __expf(acc[mt][nt][hf * 2]     * alpha) : 0.f;
                    float e1 = mrow[cl + 1] ? __expf(acc[mt][nt][hf * 2 + 1] * alpha) : 0.f;
                    rsum += e0 + e1;
                    *reinterpret_cast<uint32_t*>(outh + coff + (size_t)row * 1024 + n0 + cl)
                        = packh2(e0, e1);
                }
                rowacc[mt][hf] += rsum;
            }
        }
        float (*rs)[4] = reinterpret_cast<float(*)[4]>(dsm);
#pragma unroll
        for (int mt = 0; mt < 4; mt++)
#pragma unroll
            for (int hf = 0; hf < 2; hf++) {
                float v = rowacc[mt][hf];
                v += __shfl_xor_sync(0xffffffffu, v, 1);
                v += __shfl_xor_sync(0xffffffffu, v, 2);
                if ((lane & 3) == 0) {
                    int rl = (wy << 6) + (mt << 4) + (lane >> 2) + (hf << 3);
                    rs[rl][wx] = v;
                }
            }
        __syncthreads();
        if (tid < 128) {
            float s4 = rs[tid][0] + rs[tid][1] + rs[tid][2] + rs[tid][3];
            partial[(((size_t)blockIdx.z << 6) + (blockIdx.y << 3) + blockIdx.x) * 128 + tid] = s4;
        }
        return;
    }

    // generic epilogue
#pragma unroll
    for (int mt = 0; mt < 4; mt++) {
#pragma unroll
        for (int nt = 0; nt < 4; nt++) {
#pragma unroll
            for (int hf = 0; hf < 2; hf++) {
                int row = m0 + (wy << 6) + (mt << 4) + (lane >> 2) + (hf << 3);
                int col = n0 + (wx << 5) + (nt << 3) + ((lane & 3) << 1);
                float v0 = acc[mt][nt][hf * 2]     * alpha;
                float v1 = acc[mt][nt][hf * 2 + 1] * alpha;
                if (bias) { v0 += bias[col]; v1 += bias[col + 1]; }
                if (res) {
                    float2 rv = *reinterpret_cast<const float2*>(res + (size_t)row * ldc + col);
                    v0 += rv.x; v1 += rv.y;
                }
                if (relu) { v0 = fmaxf(v0, 0.f); v1 = fmaxf(v1, 0.f); }
                size_t oidx = coff + (size_t)row * ldc + col;
                if (cout) *reinterpret_cast<float2*>(cout + oidx) = make_float2(v0, v1);
                if (outh) *reinterpret_cast<uint32_t*>(outh + oidx) = packh2(v0, v1);
            }
        }
    }
}

// ======================= A normalization =====================================
__global__ void __launch_bounds__(256) anorm_kernel(
    const __half* __restrict__ e, const float* __restrict__ partial, float* __restrict__ A)
{
    size_t row = blockIdx.x;
    int z = (int)(row >> 10), s = (int)(row & 1023);
    size_t base = (((size_t)(z << 6) + ((s >> 7) << 3)) << 7) + (s & 127);
    float sum = 0.f;
#pragma unroll
    for (int nb = 0; nb < 8; nb++) sum += partial[base + (nb << 7)];
    float sc = g_lamscale / sum;
    int t = threadIdx.x;
#pragma unroll
    for (int i = 0; i < 2; i++) {
        int c = (t + (i << 8)) << 1;
        __half2 p = *reinterpret_cast<const __half2*>(e + row * 1024 + c);
        float2 o = make_float2(__half2float(p.x) * sc, __half2float(p.y) * sc);
        *reinterpret_cast<float2*>(A + row * 1024 + c) = o;
    }
}

// ======================= per-head LN(128) + concat ===========================
__global__ void __launch_bounds__(256) headln_kernel(
    const __half* __restrict__ O, const float* __restrict__ partial,
    const float* __restrict__ w, const float* __restrict__ bvec,
    __half* __restrict__ och)
{
    int gw = blockIdx.x * 8 + (threadIdx.x >> 5);
    int lane = threadIdx.x & 31;
    int z = gw >> 10, s_ = gw & 1023;
    size_t pbase = (((size_t)(z << 6) + ((s_ >> 7) << 3)) << 7) + (s_ & 127);
    float sum = 0.f;
#pragma unroll
    for (int nb = 0; nb < 8; nb++) sum += partial[pbase + (nb << 7)];
    float sc = g_lamscale / sum;

    const __half* xr = O + (size_t)gw * 128;
    float x0 = __half2float(xr[lane])      * sc, x1 = __half2float(xr[lane + 32]) * sc,
          x2 = __half2float(xr[lane + 64]) * sc, x3 = __half2float(xr[lane + 96]) * sc;
    float s = x0 + x1 + x2 + x3;
#pragma unroll
    for (int o = 16; o; o >>= 1) s += __shfl_xor_sync(0xffffffffu, s, o);
    float mean = s * (1.f / 128.f);
    float d0 = x0 - mean, d1 = x1 - mean, d2 = x2 - mean, d3 = x3 - mean;
    float q = d0 * d0 + d1 * d1 + d2 * d2 + d3 * d3;
#pragma unroll
    for (int o = 16; o; o >>= 1) q += __shfl_xor_sync(0xffffffffu, q, o);
    float rstd = rsqrtf(q * (1.f / 128.f) + 1e-5f);

    int h = z >> 2, b = z & 3;
    size_t base = ((size_t)(b * S_SZ + s_)) * 2048 + h * 128;
    och[base + lane]      = __float2half((d0 * rstd * w[lane]      + bvec[lane])      * HEADLN_SCALE);
    och[base + lane + 32] = __float2half((d1 * rstd * w[lane + 32] + bvec[lane + 32]) * HEADLN_SCALE);
    och[base + lane + 64] = __float2half((d2 * rstd * w[lane + 64] + bvec[lane + 64]) * HEADLN_SCALE);
    och[base + lane + 96] = __float2half((d3 * rstd * w[lane + 96] + bvec[lane + 96]) * HEADLN_SCALE);
}

// ======================= LayerNorm 1024 ======================================
__global__ void __launch_bounds__(256) ln1024(
    const float* __restrict__ X, const float* __restrict__ w,
    const float* __restrict__ bvec, float* __restrict__ out,
    __half* __restrict__ outh)
{
    __shared__ float red[8];
    __shared__ float bc;
    size_t row = blockIdx.x;
    const float* xr = X + row * 1024;
    int t = threadIdx.x;
    int wid = t >> 5, lane = t & 31;

    float v[4];
    float s = 0.f;
#pragma unroll
    for (int i = 0; i < 4; i++) { v[i] = xr[t + i * 256]; s += v[i]; }
#pragma unroll
    for (int o = 16; o; o >>= 1) s += __shfl_xor_sync(0xffffffffu, s, o);
    if (lane == 0) red[wid] = s;
    __syncthreads();
    if (t < 32) {
        float s2 = (t < 8) ? red[t] : 0.f;
#pragma unroll
        for (int o = 4; o; o >>= 1) s2 += __shfl_xor_sync(0xffffffffu, s2, o);
        if (t == 0) bc = s2 * (1.f / 1024.f);
    }
    __syncthreads();
    float mean = bc;

    float q = 0.f;
#pragma unroll
    for (int i = 0; i < 4; i++) { float d = v[i] - mean; q += d * d; }
#pragma unroll
    for (int o = 16; o; o >>= 1) q += __shfl_xor_sync(0xffffffffu, q, o);
    __syncthreads();
    if (lane == 0) red[wid] = q;
    __syncthreads();
    if (t < 32) {
        float q2 = (t < 8) ? red[t] : 0.f;
#pragma unroll
        for (int o = 4; o; o >>= 1) q2 += __shfl_xor_sync(0xffffffffu, q2, o);
        if (t == 0) bc = rsqrtf(q2 * (1.f / 1024.f) + 1e-5f);
    }
    __syncthreads();
    float rstd = bc;
#pragma unroll
    for (int i = 0; i < 4; i++) {
        int c = t + i * 256;
        float vv = (v[i] - mean) * rstd * w[c] + bvec[c];
        out[row * 1024 + c] = vv;
        if (outh) outh[row * 1024 + c] = __float2half(vv);
    }
}

// ======================= host launcher ======================================
extern "C" void kernel_launch(void* const* d_in, const int* in_sizes, int n_in,
                              void* d_out, int out_size)
{
    const float* x    = (const float*)d_in[0];
    const int*   mask = (const int*)  d_in[1];
    const float* WQ1  = (const float*)d_in[2];
    const float* bQ1  = (const float*)d_in[3];
    const float* WK1  = (const float*)d_in[4];
    const float* bK1  = (const float*)d_in[5];
    const float* WV   = (const float*)d_in[6];
    const float* bV   = (const float*)d_in[7];
    const float* lnhw = (const float*)d_in[8];
    const float* lnhb = (const float*)d_in[9];
    const float* WO   = (const float*)d_in[10];
    const float* bO   = (const float*)d_in[11];
    const float* ln1w = (const float*)d_in[12];
    const float* ln1b = (const float*)d_in[13];
    const float* ln2w = (const float*)d_in[14];
    const float* ln2b = (const float*)d_in[15];
    const float* W1   = (const float*)d_in[16];
    const float* b1   = (const float*)d_in[17];
    const float* W2   = (const float*)d_in[18];
    const float* b2   = (const float*)d_in[19];
    const float* lq1  = (const float*)d_in[20];
    const float* lk1  = (const float*)d_in[21];
    const float* lq2  = (const float*)d_in[22];
    const float* lk2  = (const float*)d_in[23];

    float* out = (float*)d_out;

    const int SMEM = 3 * 2 * TILEB;   // 110592: 3-stage, BK=64
    cudaFuncSetAttribute(gemm_mma<3, 0>, cudaFuncAttributeMaxDynamicSharedMemorySize, SMEM);
    cudaFuncSetAttribute(gemm_mma<3, 1>, cudaFuncAttributeMaxDynamicSharedMemorySize, SMEM);
    cudaFuncSetAttribute(gemm_mma<3, 2>, cudaFuncAttributeMaxDynamicSharedMemorySize, SMEM);

    float *h1pre, *h1, *r2pre, *biasqkv, *part;
    __half *qkvh, *bw, *woth, *w1th, *w2th;
    __half *xhf, *ah, *vth, *oph, *och, *h1h, *ffhh;
    cudaGetSymbolAddress((void**)&qkvh,  g_QKVh);
    cudaGetSymbolAddress((void**)&bw,    g_Bw);
    cudaGetSymbolAddress((void**)&woth,  g_WOth);
    cudaGetSymbolAddress((void**)&w1th,  g_W1th);
    cudaGetSymbolAddress((void**)&w2th,  g_W2th);
    cudaGetSymbolAddress((void**)&biasqkv, g_biasqkv);
    cudaGetSymbolAddress((void**)&xhf,   g_xhf);
    cudaGetSymbolAddress((void**)&ah,    g_Ah);
    cudaGetSymbolAddress((void**)&part,  g_part);
    cudaGetSymbolAddress((void**)&vth,   g_Vth);
    cudaGetSymbolAddress((void**)&oph,   g_O);
    cudaGetSymbolAddress((void**)&och,   g_Och);
    cudaGetSymbolAddress((void**)&h1pre, g_h1pre);
    cudaGetSymbolAddress((void**)&h1,    g_h1);
    cudaGetSymbolAddress((void**)&h1h,   g_h1h);
    cudaGetSymbolAddress((void**)&ffhh,  g_ffhh);
    cudaGetSymbolAddress((void**)&r2pre, g_r2pre);

    lam_kernel<<<1, 64>>>(lq1, lk1, lq2, lk2);
    concat_bias3<<<16, 256>>>(bQ1, bK1, bV, biasqkv);
    convW_all<<<14336, dim3(32, 8)>>>(WQ1, WK1, WV, WO, W1, W2, bw, woth, w1th, w2th);
    conv_h_f16<<<4096, 256>>>(x, xhf, 1048576);

    // fused QKV projection: [4096, 4096], K=1024
    gemm_mma<3, 0><<<dim3(32, 32, 1), 256, SMEM>>>(
        xhf, bw, biasqkv, nullptr, nullptr, qkvh, nullptr, nullptr,
        1024, 1024, 1024, 4096, 1.0f, 0);

    // scores + fused exp: K=64 -> single iteration
    gemm_mma<3, 1><<<dim3(8, 8, 64), 256, SMEM>>>(
        qkvh, qkvh + 1024, nullptr, nullptr, nullptr, ah, part, mask,
        64, 4096, 4096, 1024, 0.03125f, 0);

    // A output (fp32, normalized)
    if (out_size >= FULL_ELEMS)
        anorm_kernel<<<65536, 256>>>(ah, part, out + R2_ELEMS);

    convVt_f16<<<dim3(32, 4, 64), dim3(32, 8)>>>(qkvh, vth);

    // AV on unnormalized e -> fp16 O
    gemm_mma<3, 2><<<dim3(1, 8, 64), 256, SMEM>>>(
        ah, vth, nullptr, nullptr, nullptr, oph, nullptr, nullptr,
        1024, 1024, 1024, 128, 1.0f, 0);

    headln_kernel<<<8192, 256>>>(oph, part, lnhw, lnhb, och);

    // output projection + residual(x), LN1
    gemm_mma<3, 0><<<dim3(8, 32, 1), 256, SMEM>>>(
        och, woth, bO, x, h1pre, nullptr, nullptr, nullptr,
        2048, 2048, 2048, 1024, 1.0f, 0);
    ln1024<<<4096, 256>>>(h1pre, ln1w, ln1b, h1, h1h);

    // FFN: relu(h1 @ W1 + b1) @ W2 + b2 + h1, LN2 -> out
    gemm_mma<3, 0><<<dim3(32, 32, 1), 256, SMEM>>>(
        h1h, w1th, b1, nullptr, nullptr, ffhh, nullptr, nullptr,
        1024, 1024, 1024, 4096, 1.0f, 1);
    gemm_mma<3, 0><<<dim3(8, 32, 1), 256, SMEM>>>(
        ffhh, w2th, b2, h1, r2pre, nullptr, nullptr, nullptr,
        4096, 4096, 4096, 1024, 1.0f, 0);
    ln1024<<<4096, 256>>>(r2pre, ln2w, ln2b, out, nullptr);
}

// round 17
// speedup vs baseline: 2.1390x; 1.1095x over previous
#include <cuda_runtime.h>
#include <cuda_fp16.h>
#include <math.h>
#include <stddef.h>
#include <stdint.h>

#define B_SZ   4
#define S_SZ   1024
#define D_M    1024
#define H_N    16
#define D_INT  64
#define D_V    128
#define HID    4096
#define NTOK   4096
#define HB     64
#define LAMBDA_INIT 0.3555090675909693f
#define HEADLN_SCALE 0.6444909324090307f
#define R2_ELEMS 4194304
#define FULL_ELEMS 71303168

// ======================= helpers =======================
__device__ __forceinline__ uint32_t smem_u32(const void* p) {
    uint32_t a;
    asm("{ .reg .u64 t; cvta.to.shared.u64 t, %1; cvt.u32.u64 %0, t; }" : "=r"(a) : "l"(p));
    return a;
}
#define CP_ASYNC16(sdst, gsrc) \
    asm volatile("cp.async.cg.shared.global [%0], [%1], 16;" :: "r"(sdst), "l"(gsrc) : "memory")
#define CP_COMMIT() asm volatile("cp.async.commit_group;" ::: "memory")
template<int N> __device__ __forceinline__ void cp_waitg() {
    asm volatile("cp.async.wait_group %0;" :: "n"(N) : "memory");
}

__device__ __forceinline__ void mma_f16(float* d, uint32_t a0, uint32_t a1, uint32_t a2,
                                        uint32_t a3, uint32_t b0, uint32_t b1) {
    asm volatile(
        "mma.sync.aligned.m16n8k16.row.col.f32.f16.f16.f32 "
        "{%0,%1,%2,%3}, {%4,%5,%6,%7}, {%8,%9}, {%0,%1,%2,%3};"
        : "+f"(d[0]), "+f"(d[1]), "+f"(d[2]), "+f"(d[3])
        : "r"(a0), "r"(a1), "r"(a2), "r"(a3), "r"(b0), "r"(b1));
}
__device__ __forceinline__ void ldmx4(uint32_t* r, uint32_t addr) {
    asm volatile("ldmatrix.sync.aligned.m8n8.x4.shared.b16 {%0,%1,%2,%3}, [%4];"
        : "=r"(r[0]), "=r"(r[1]), "=r"(r[2]), "=r"(r[3]) : "r"(addr));
}
__device__ __forceinline__ uint32_t packh2(float a, float b) {
    __half2 p; p.x = __float2half(a); p.y = __float2half(b);
    return *reinterpret_cast<uint32_t*>(&p);
}

// BK=64 tile geometry: 128 rows x 144 bytes (128 data + 16 pad)
#define ROWB 144
#define TILEB 18432

// ======================= static scratch =======================
__device__ __align__(16) __half  g_QKVh [(size_t)NTOK * 4096];   // Q|K|V fp16 hi
__device__ __align__(16) __half  g_Bw   [(size_t)4096 * 1024];   // WQ|WK|WV K-major fp16
__device__ __align__(16) __half  g_WOth [(size_t)1024 * 2048];
__device__ __align__(16) __half  g_W1th [(size_t)4096 * 1024];
__device__ __align__(16) __half  g_W2th [(size_t)1024 * 4096];
__device__ __align__(16) float   g_biasqkv[4096];
__device__ __align__(16) __half  g_xhf  [(size_t)NTOK * 1024];
__device__ __align__(16) __half  g_Ah   [(size_t)HB * S_SZ * S_SZ];  // unnormalized exp, fp16
__device__ __align__(16) float   g_part [(size_t)HB * 8 * 8 * 128];  // per-CTA row partial sums
__device__ __align__(16) float   g_scsum[(size_t)HB * S_SZ];         // lamscale/rowsum
__device__ __align__(16) __half  g_Vth  [(size_t)HB * 128 * 1024];
__device__ __align__(16) __half  g_O    [(size_t)HB * S_SZ * D_V];   // unnormalized O, fp16
__device__ __align__(16) __half  g_Och  [(size_t)NTOK * 2048];
__device__ __align__(16) float   g_h1pre[(size_t)NTOK * D_M];
__device__ __align__(16) float   g_h1   [(size_t)NTOK * D_M];
__device__ __align__(16) __half  g_h1h  [(size_t)NTOK * D_M];
__device__ __align__(16) __half  g_ffhh [(size_t)NTOK * HID];
__device__ __align__(16) float   g_r2pre[(size_t)NTOK * D_M];
__device__ float g_lamscale;

// ======================= lambda =======================
__global__ void lam_kernel(const float* __restrict__ lq1, const float* __restrict__ lk1,
                           const float* __restrict__ lq2, const float* __restrict__ lk2)
{
    __shared__ float s1[64], s2[64];
    int t = threadIdx.x;
    s1[t] = lq1[t] * lk1[t];
    s2[t] = lq2[t] * lk2[t];
    __syncthreads();
    if (t == 0) {
        float d1 = 0.f, d2 = 0.f;
        for (int i = 0; i < 64; i++) { d1 += s1[i]; d2 += s2[i]; }
        g_lamscale = 1.0f - (expf(d1) - expf(d2) + LAMBDA_INIT);
    }
}

// ======================= conversions =======================
__global__ void __launch_bounds__(256) conv_h_f16(
    const float* __restrict__ in, __half* __restrict__ oh, int n4)
{
    int i = blockIdx.x * 256 + threadIdx.x;
    if (i >= n4) return;
    float4 v = reinterpret_cast<const float4*>(in)[i];
    reinterpret_cast<uint32_t*>(oh)[i * 2]     = packh2(v.x, v.y);
    reinterpret_cast<uint32_t*>(oh)[i * 2 + 1] = packh2(v.z, v.w);
}

__global__ void convW_all(
    const float* __restrict__ WQ1, const float* __restrict__ WK1, const float* __restrict__ WV,
    const float* __restrict__ WO,  const float* __restrict__ W1,  const float* __restrict__ W2,
    __half* __restrict__ bw, __half* __restrict__ woth,
    __half* __restrict__ w1th, __half* __restrict__ w2th)
{
    __shared__ float t[32][33];
    int lb = blockIdx.x;
    const float* in; __half* oh; int K, dout, gxm;
    if      (lb < 1024)  { in = WQ1; oh = bw;                  K = 1024; dout = 64;   gxm = 32;  }
    else if (lb < 2048)  { in = WK1; oh = bw + 1024 * 1024;    K = 1024; dout = 64;   gxm = 32;  lb -= 1024; }
    else if (lb < 4096)  { in = WV;  oh = bw + 2048 * 1024;    K = 1024; dout = 128;  gxm = 32;  lb -= 2048; }
    else if (lb < 6144)  { in = WO;  oh = woth;                K = 2048; dout = 1024; gxm = 64;  lb -= 4096; }
    else if (lb < 10240) { in = W1;  oh = w1th;                K = 1024; dout = 4096; gxm = 32;  lb -= 6144; }
    else                 { in = W2;  oh = w2th;                K = 4096; dout = 1024; gxm = 128; lb -= 10240; }
    int gx = lb % gxm, gy = lb / gxm;
    int k0 = gx * 32, n0 = gy * 32;
    int h = n0 / dout, d0 = n0 - h * dout;
    const float* src = in + (size_t)h * K * dout + d0;
    for (int r = threadIdx.y; r < 32; r += 8)
        t[r][threadIdx.x] = src[(size_t)(k0 + r) * dout + threadIdx.x];
    __syncthreads();
    for (int r = threadIdx.y; r < 32; r += 8)
        oh[(size_t)(n0 + r) * K + k0 + threadIdx.x] = __float2half(t[threadIdx.x][r]);
}

__global__ void convVt_f16(const __half* __restrict__ sh, __half* __restrict__ oh)
{
    __shared__ __half th[32][33];
    int z = blockIdx.z, h = z >> 2, b = z & 3;
    int t0 = blockIdx.x * 32, v0 = blockIdx.y * 32;
    for (int r = threadIdx.y; r < 32; r += 8)
        th[r][threadIdx.x] = sh[(size_t)(b * 1024 + t0 + r) * 4096 + 2048 + h * 128 + v0 + threadIdx.x];
    __syncthreads();
    size_t base = (size_t)z * 131072;
    for (int r = threadIdx.y; r < 32; r += 8)
        oh[base + (size_t)(v0 + r) * 1024 + t0 + threadIdx.x] = th[threadIdx.x][r];
}

__global__ void concat_bias3(const float* __restrict__ bq, const float* __restrict__ bk,
                             const float* __restrict__ bv, float* __restrict__ o)
{
    int t = blockIdx.x * 256 + threadIdx.x;
    if (t < 1024) o[t] = bq[t];
    else if (t < 2048) o[t] = bk[t - 1024];
    else if (t < 4096) o[t] = bv[t - 2048];
}

// row scale: scsum[r] = lamscale / rowsum(partials)
__global__ void __launch_bounds__(256) rowsum_kernel(
    const float* __restrict__ partial, float* __restrict__ scsum)
{
    int r = blockIdx.x * 256 + threadIdx.x;
    int z = r >> 10, s = r & 1023;
    size_t base = (((size_t)(z << 6) + ((s >> 7) << 3)) << 7) + (s & 127);
    float sum = 0.f;
#pragma unroll
    for (int nb = 0; nb < 8; nb++) sum += partial[base + (nb << 7)];
    scsum[r] = g_lamscale / sum;
}

// ======================= tensor-core GEMM (fp16 mma.sync, BK=64) ============
// MODE 0: plain GEMM. MODE 1: scores, fused exp epilogue. MODE 2: AV batched
// (optionally streams normalized fp32 A out of the e tiles; partial = scsum).
template<int NS, int MODE>
__global__ void __launch_bounds__(256, 2) gemm_mma(
    const __half* __restrict__ Ah, const __half* __restrict__ Bh,
    const float* __restrict__ bias, const float* __restrict__ res,
    float* __restrict__ cout, __half* __restrict__ outh,
    float* __restrict__ partial, const int* __restrict__ mask,
    int K, int lda, int ldb, int ldc, float alpha, int relu)
{
    constexpr int STG = 2 * TILEB;
    extern __shared__ char dsm[];
    const int tid = threadIdx.x;
    const int lane = tid & 31, wid = tid >> 5;
    const int wy = wid >> 2, wx = wid & 3;       // warp tile: 64(M) x 32(N)
    const int m0 = blockIdx.y * 128, n0 = blockIdx.x * 128;
    const uint32_t smbase = smem_u32(dsm);

    size_t aoff = 0, boff = 0, coff = 0;
    if (MODE == 1) {
        int z = blockIdx.z, h = z >> 2, b = z & 3;
        aoff = (size_t)(b << 10) * lda + (h << 6);
        boff = (size_t)(b << 10) * ldb + (h << 6);
        coff = (size_t)z << 20;
    } else if (MODE == 2) {
        int z = blockIdx.z;
        aoff = (size_t)z << 20;
        boff = (size_t)z << 17;
        coff = (size_t)z << 17;
    }

    // MODE 2: per-row A scales in smem past the pipeline stages
    float* sc_s = reinterpret_cast<float*>(dsm + NS * STG);
    if (MODE == 2 && cout && tid < 128)
        sc_s[tid] = partial[((size_t)blockIdx.z << 10) + m0 + tid];

    float acc[4][4][4];
#pragma unroll
    for (int i = 0; i < 4; i++)
#pragma unroll
        for (int j = 0; j < 4; j++)
#pragma unroll
            for (int q = 0; q < 4; q++) acc[i][j][q] = 0.f;

    const int niter = K >> 6;

    auto issue_tile = [&](int it, int slot) {
        int k0 = it << 6;
        uint32_t sb = smbase + slot * STG;
#pragma unroll
        for (int i = 0; i < 4; i++) {
            int l = tid + (i << 8);
            int row = l >> 3, c16 = l & 7;
            size_t aidx = aoff + (size_t)(m0 + row) * lda + k0 + (c16 << 3);
            size_t bidx = boff + (size_t)(n0 + row) * ldb + k0 + (c16 << 3);
            uint32_t so = (uint32_t)(row * ROWB + (c16 << 4));
            CP_ASYNC16(sb + so,         Ah + aidx);
            CP_ASYNC16(sb + TILEB + so, Bh + bidx);
        }
        CP_COMMIT();
    };

#pragma unroll
    for (int s = 0; s < NS - 1; s++)
        if (s < niter) issue_tile(s, s);

    const int a_row = (wy << 6) + (lane & 7) + ((lane >> 3) & 1) * 8;  // + mt*16
    const int a_kb  = (lane >> 4) << 4;
    const int b_row8 = (wx << 5) + (lane & 7);                         // + nt*8
    const int b_k4   = ((lane >> 3) & 3) << 4;

    int cs = 0, is_ = NS - 1;
#pragma unroll 1
    for (int it = 0; it < niter; it++) {
        // single-sync pipeline: wait -> sync -> issue -> consume
        if (it < niter - 1) cp_waitg<NS - 2>(); else cp_waitg<0>();
        __syncthreads();
        if (it + NS - 1 < niter) issue_tile(it + NS - 1, is_);

        uint32_t pAh = smbase + cs * STG;
        uint32_t pBh = pAh + TILEB;

#pragma unroll
        for (int half = 0; half < 2; half++) {
            const int hb = half << 6;
            uint32_t b4[4][4];
#pragma unroll
            for (int nt = 0; nt < 4; nt++) {
                uint32_t bo = (uint32_t)((b_row8 + (nt << 3)) * ROWB + hb + b_k4);
                ldmx4(b4[nt], pBh + bo);
            }
#pragma unroll
            for (int ks = 0; ks < 2; ks++) {
                const int ksb = hb + (ks << 5);
#pragma unroll
                for (int mt = 0; mt < 4; mt++) {
                    uint32_t ao = (uint32_t)((a_row + (mt << 4)) * ROWB + ksb + a_kb);
                    uint32_t ahf[4];
                    ldmx4(ahf, pAh + ao);
#pragma unroll
                    for (int nt = 0; nt < 4; nt++)
                        mma_f16(acc[mt][nt], ahf[0], ahf[1], ahf[2], ahf[3],
                                b4[nt][ks * 2], b4[nt][ks * 2 + 1]);
                }
            }
        }

        // MODE 2: stream normalized fp32 A from the staged e tile
        if (MODE == 2 && cout) {
            const char* tp = dsm + cs * STG;
            size_t abase = ((size_t)blockIdx.z << 20) + (size_t)m0 * 1024 + (it << 6);
#pragma unroll
            for (int i = 0; i < 8; i++) {
                int idx = tid + (i << 8);           // 0..2047
                int rr = idx >> 4, c4 = (idx & 15) << 2;
                const __half* hp = reinterpret_cast<const __half*>(tp + rr * ROWB + (c4 << 1));
                float sc = sc_s[rr];
                float4 o = make_float4(__half2float(hp[0]) * sc, __half2float(hp[1]) * sc,
                                       __half2float(hp[2]) * sc, __half2float(hp[3]) * sc);
                *reinterpret_cast<float4*>(cout + abase + (size_t)rr * 1024 + c4) = o;
            }
        }

        cs = (cs + 1 == NS) ? 0 : cs + 1;
        is_ = (is_ + 1 == NS) ? 0 : is_ + 1;
    }

    if (MODE == 1) {
        // fused exp + row-partial-sum epilogue (|s|<1, exp safe)
        const int b = blockIdx.z & 3;
        const int* mrow = mask + (b << 10) + n0;
        float rowacc[4][2];
#pragma unroll
        for (int mt = 0; mt < 4; mt++) { rowacc[mt][0] = 0.f; rowacc[mt][1] = 0.f; }
#pragma unroll
        for (int mt = 0; mt < 4; mt++) {
#pragma unroll
            for (int hf = 0; hf < 2; hf++) {
                int row = m0 + (mt << 4) + (wy << 6) + (lane >> 2) + (hf << 3);
                float rsum = 0.f;
#pragma unroll
                for (int nt = 0; nt < 4; nt++) {
                    int cl = (wx << 5) + (nt << 3) + ((lane & 3) << 1);
                    float e0 = mrow[cl]     ? __expf(acc[mt][nt][hf * 2]     * alpha) : 0.f;
                    float e1 = mrow[cl + 1] ? __expf(acc[mt][nt][hf * 2 + 1] * alpha) : 0.f;
                    rsum += e0 + e1;
                    *reinterpret_cast<uint32_t*>(outh + coff + (size_t)row * 1024 + n0 + cl)
                        = packh2(e0, e1);
                }
                rowacc[mt][hf] += rsum;
            }
        }
        __syncthreads();   // tile smem reuse as reduction scratch
        float (*rs)[4] = reinterpret_cast<float(*)[4]>(dsm);
#pragma unroll
        for (int mt = 0; mt < 4; mt++)
#pragma unroll
            for (int hf = 0; hf < 2; hf++) {
                float v = rowacc[mt][hf];
                v += __shfl_xor_sync(0xffffffffu, v, 1);
                v += __shfl_xor_sync(0xffffffffu, v, 2);
                if ((lane & 3) == 0) {
                    int rl = (wy << 6) + (mt << 4) + (lane >> 2) + (hf << 3);
                    rs[rl][wx] = v;
                }
            }
        __syncthreads();
        if (tid < 128) {
            float s4 = rs[tid][0] + rs[tid][1] + rs[tid][2] + rs[tid][3];
            partial[(((size_t)blockIdx.z << 6) + (blockIdx.y << 3) + blockIdx.x) * 128 + tid] = s4;
        }
        return;
    }

    // generic epilogue
#pragma unroll
    for (int mt = 0; mt < 4; mt++) {
#pragma unroll
        for (int nt = 0; nt < 4; nt++) {
#pragma unroll
            for (int hf = 0; hf < 2; hf++) {
                int row = m0 + (wy << 6) + (mt << 4) + (lane >> 2) + (hf << 3);
                int col = n0 + (wx << 5) + (nt << 3) + ((lane & 3) << 1);
                float v0 = acc[mt][nt][hf * 2]     * alpha;
                float v1 = acc[mt][nt][hf * 2 + 1] * alpha;
                if (bias) { v0 += bias[col]; v1 += bias[col + 1]; }
                if (res) {
                    float2 rv = *reinterpret_cast<const float2*>(res + (size_t)row * ldc + col);
                    v0 += rv.x; v1 += rv.y;
                }
                if (relu) { v0 = fmaxf(v0, 0.f); v1 = fmaxf(v1, 0.f); }
                size_t oidx = coff + (size_t)row * ldc + col;
                if (MODE == 0 && cout) *reinterpret_cast<float2*>(cout + oidx) = make_float2(v0, v1);
                if (outh) *reinterpret_cast<uint32_t*>(outh + oidx) = packh2(v0, v1);
            }
        }
    }
}

// ======================= per-head LN(128) + concat ===========================
__global__ void __launch_bounds__(256) headln_kernel(
    const __half* __restrict__ O, const float* __restrict__ scsum,
    const float* __restrict__ w, const float* __restrict__ bvec,
    __half* __restrict__ och)
{
    int gw = blockIdx.x * 8 + (threadIdx.x >> 5);
    int lane = threadIdx.x & 31;
    int z = gw >> 10, s_ = gw & 1023;
    float sc = scsum[gw];

    const __half* xr = O + (size_t)gw * 128;
    float x0 = __half2float(xr[lane])      * sc, x1 = __half2float(xr[lane + 32]) * sc,
          x2 = __half2float(xr[lane + 64]) * sc, x3 = __half2float(xr[lane + 96]) * sc;
    float s = x0 + x1 + x2 + x3;
#pragma unroll
    for (int o = 16; o; o >>= 1) s += __shfl_xor_sync(0xffffffffu, s, o);
    float mean = s * (1.f / 128.f);
    float d0 = x0 - mean, d1 = x1 - mean, d2 = x2 - mean, d3 = x3 - mean;
    float q = d0 * d0 + d1 * d1 + d2 * d2 + d3 * d3;
#pragma unroll
    for (int o = 16; o; o >>= 1) q += __shfl_xor_sync(0xffffffffu, q, o);
    float rstd = rsqrtf(q * (1.f / 128.f) + 1e-5f);

    int h = z >> 2, b = z & 3;
    size_t base = ((size_t)(b * S_SZ + s_)) * 2048 + h * 128;
    och[base + lane]      = __float2half((d0 * rstd * w[lane]      + bvec[lane])      * HEADLN_SCALE);
    och[base + lane + 32] = __float2half((d1 * rstd * w[lane + 32] + bvec[lane + 32]) * HEADLN_SCALE);
    och[base + lane + 64] = __float2half((d2 * rstd * w[lane + 64] + bvec[lane + 64]) * HEADLN_SCALE);
    och[base + lane + 96] = __float2half((d3 * rstd * w[lane + 96] + bvec[lane + 96]) * HEADLN_SCALE);
}

// ======================= LayerNorm 1024 ======================================
__global__ void __launch_bounds__(256) ln1024(
    const float* __restrict__ X, const float* __restrict__ w,
    const float* __restrict__ bvec, float* __restrict__ out,
    __half* __restrict__ outh)
{
    __shared__ float red[8];
    __shared__ float bc;
    size_t row = blockIdx.x;
    const float* xr = X + row * 1024;
    int t = threadIdx.x;
    int wid = t >> 5, lane = t & 31;

    float v[4];
    float s = 0.f;
#pragma unroll
    for (int i = 0; i < 4; i++) { v[i] = xr[t + i * 256]; s += v[i]; }
#pragma unroll
    for (int o = 16; o; o >>= 1) s += __shfl_xor_sync(0xffffffffu, s, o);
    if (lane == 0) red[wid] = s;
    __syncthreads();
    if (t < 32) {
        float s2 = (t < 8) ? red[t] : 0.f;
#pragma unroll
        for (int o = 4; o; o >>= 1) s2 += __shfl_xor_sync(0xffffffffu, s2, o);
        if (t == 0) bc = s2 * (1.f / 1024.f);
    }
    __syncthreads();
    float mean = bc;

    float q = 0.f;
#pragma unroll
    for (int i = 0; i < 4; i++) { float d = v[i] - mean; q += d * d; }
#pragma unroll
    for (int o = 16; o; o >>= 1) q += __shfl_xor_sync(0xffffffffu, q, o);
    __syncthreads();
    if (lane == 0) red[wid] = q;
    __syncthreads();
    if (t < 32) {
        float q2 = (t < 8) ? red[t] : 0.f;
#pragma unroll
        for (int o = 4; o; o >>= 1) q2 += __shfl_xor_sync(0xffffffffu, q2, o);
        if (t == 0) bc = rsqrtf(q2 * (1.f / 1024.f) + 1e-5f);
    }
    __syncthreads();
    float rstd = bc;
#pragma unroll
    for (int i = 0; i < 4; i++) {
        int c = t + i * 256;
        float vv = (v[i] - mean) * rstd * w[c] + bvec[c];
        out[row * 1024 + c] = vv;
        if (outh) outh[row * 1024 + c] = __float2half(vv);
    }
}

// ======================= host launcher ======================================
extern "C" void kernel_launch(void* const* d_in, const int* in_sizes, int n_in,
                              void* d_out, int out_size)
{
    const float* x    = (const float*)d_in[0];
    const int*   mask = (const int*)  d_in[1];
    const float* WQ1  = (const float*)d_in[2];
    const float* bQ1  = (const float*)d_in[3];
    const float* WK1  = (const float*)d_in[4];
    const float* bK1  = (const float*)d_in[5];
    const float* WV   = (const float*)d_in[6];
    const float* bV   = (const float*)d_in[7];
    const float* lnhw = (const float*)d_in[8];
    const float* lnhb = (const float*)d_in[9];
    const float* WO   = (const float*)d_in[10];
    const float* bO   = (const float*)d_in[11];
    const float* ln1w = (const float*)d_in[12];
    const float* ln1b = (const float*)d_in[13];
    const float* ln2w = (const float*)d_in[14];
    const float* ln2b = (const float*)d_in[15];
    const float* W1   = (const float*)d_in[16];
    const float* b1   = (const float*)d_in[17];
    const float* W2   = (const float*)d_in[18];
    const float* b2   = (const float*)d_in[19];
    const float* lq1  = (const float*)d_in[20];
    const float* lk1  = (const float*)d_in[21];
    const float* lq2  = (const float*)d_in[22];
    const float* lk2  = (const float*)d_in[23];

    float* out = (float*)d_out;

    const int SMEM = 3 * 2 * TILEB + 512;   // 3-stage BK=64 + sc_s
    cudaFuncSetAttribute(gemm_mma<3, 0>, cudaFuncAttributeMaxDynamicSharedMemorySize, SMEM);
    cudaFuncSetAttribute(gemm_mma<3, 1>, cudaFuncAttributeMaxDynamicSharedMemorySize, SMEM);
    cudaFuncSetAttribute(gemm_mma<3, 2>, cudaFuncAttributeMaxDynamicSharedMemorySize, SMEM);

    float *h1pre, *h1, *r2pre, *biasqkv, *part, *scsum;
    __half *qkvh, *bw, *woth, *w1th, *w2th;
    __half *xhf, *ah, *vth, *oph, *och, *h1h, *ffhh;
    cudaGetSymbolAddress((void**)&qkvh,  g_QKVh);
    cudaGetSymbolAddress((void**)&bw,    g_Bw);
    cudaGetSymbolAddress((void**)&woth,  g_WOth);
    cudaGetSymbolAddress((void**)&w1th,  g_W1th);
    cudaGetSymbolAddress((void**)&w2th,  g_W2th);
    cudaGetSymbolAddress((void**)&biasqkv, g_biasqkv);
    cudaGetSymbolAddress((void**)&xhf,   g_xhf);
    cudaGetSymbolAddress((void**)&ah,    g_Ah);
    cudaGetSymbolAddress((void**)&part,  g_part);
    cudaGetSymbolAddress((void**)&scsum, g_scsum);
    cudaGetSymbolAddress((void**)&vth,   g_Vth);
    cudaGetSymbolAddress((void**)&oph,   g_O);
    cudaGetSymbolAddress((void**)&och,   g_Och);
    cudaGetSymbolAddress((void**)&h1pre, g_h1pre);
    cudaGetSymbolAddress((void**)&h1,    g_h1);
    cudaGetSymbolAddress((void**)&h1h,   g_h1h);
    cudaGetSymbolAddress((void**)&ffhh,  g_ffhh);
    cudaGetSymbolAddress((void**)&r2pre, g_r2pre);

    lam_kernel<<<1, 64>>>(lq1, lk1, lq2, lk2);
    concat_bias3<<<16, 256>>>(bQ1, bK1, bV, biasqkv);
    convW_all<<<14336, dim3(32, 8)>>>(WQ1, WK1, WV, WO, W1, W2, bw, woth, w1th, w2th);
    conv_h_f16<<<4096, 256>>>(x, xhf, 1048576);

    // fused QKV projection: [4096, 4096], K=1024
    gemm_mma<3, 0><<<dim3(32, 32, 1), 256, SMEM>>>(
        xhf, bw, biasqkv, nullptr, nullptr, qkvh, nullptr, nullptr,
        1024, 1024, 1024, 4096, 1.0f, 0);

    // scores + fused exp: K=64 -> single iteration
    gemm_mma<3, 1><<<dim3(8, 8, 64), 256, SMEM>>>(
        qkvh, qkvh + 1024, nullptr, nullptr, nullptr, ah, part, mask,
        64, 4096, 4096, 1024, 0.03125f, 0);

    rowsum_kernel<<<256, 256>>>(part, scsum);
    convVt_f16<<<dim3(32, 4, 64), dim3(32, 8)>>>(qkvh, vth);

    // AV on unnormalized e -> fp16 O; also streams normalized fp32 A
    float* A_ptr = (out_size >= FULL_ELEMS) ? (out + R2_ELEMS) : nullptr;
    gemm_mma<3, 2><<<dim3(1, 8, 64), 256, SMEM>>>(
        ah, vth, nullptr, nullptr, A_ptr, oph, scsum, nullptr,
        1024, 1024, 1024, 128, 1.0f, 0);

    headln_kernel<<<8192, 256>>>(oph, scsum, lnhw, lnhb, och);

    // output projection + residual(x), LN1
    gemm_mma<3, 0><<<dim3(8, 32, 1), 256, SMEM>>>(
        och, woth, bO, x, h1pre, nullptr, nullptr, nullptr,
        2048, 2048, 2048, 1024, 1.0f, 0);
    ln1024<<<4096, 256>>>(h1pre, ln1w, ln1b, h1, h1h);

    // FFN: relu(h1 @ W1 + b1) @ W2 + b2 + h1, LN2 -> out
    gemm_mma<3, 0><<<dim3(32, 32, 1), 256, SMEM>>>(
        h1h, w1th, b1, nullptr, nullptr, ffhh, nullptr, nullptr,
        1024, 1024, 1024, 4096, 1.0f, 1);
    gemm_mma<3, 0><<<dim3(8, 32, 1), 256, SMEM>>>(
        ffhh, w2th, b2, h1, r2pre, nullptr, nullptr, nullptr,
        4096, 4096, 4096, 1024, 1.0f, 0);
    ln1024<<<4096, 256>>>(r2pre, ln2w, ln2b, out, nullptr);
}